// round 13
// baseline (speedup 1.0000x reference)
#include <cuda_runtime.h>
#include <cstdint>
#include <cstddef>

#define BATCH 2
#define CCH   256
#define NPIX  4096
#define NHEAD 4
#define DDIM  64
#define NCHUNK 64

// ---------------- scratch ----------------
__device__ float g_q    [BATCH * CCH     * NPIX];
__device__ float g_kv   [BATCH * 2*CCH   * NPIX];
__device__ float g_kvdw [BATCH * 2*CCH   * NPIX];
__device__ float g_attn [BATCH * CCH     * NPIX];
__device__ float g_g1   [BATCH * 64      * NPIX];
__device__ float g_g2   [BATCH * 64      * NPIX];
__device__ float g_gated[BATCH * CCH     * NPIX];
__device__ float g_S    [BATCH * NHEAD * NCHUNK * DDIM * DDIM];
__device__ float g_ksum [BATCH * NHEAD * NCHUNK * DDIM];

// pre-split weights, hi/lo INTERLEAVED float2: g_Wsp[2*(off + o*K + k)] = {hi, lo}
#define OFF_Q  0
#define OFF_A1 65536
#define OFF_G1 196608
#define OFF_G2 212992
#define OFF_G3 249856
#define OFF_O  266240
#define W_TOTAL 331776
__device__ float g_Wsp[2 * W_TOTAL];

// ---------------- streams/events (created at load, outside kernel_launch) ----------
struct StreamInit {
    cudaStream_t s1;
    cudaEvent_t evFork, evQ, evGate;
    StreamInit() {
        cudaStreamCreateWithFlags(&s1, cudaStreamNonBlocking);
        cudaEventCreateWithFlags(&evFork, cudaEventDisableTiming);
        cudaEventCreateWithFlags(&evQ,    cudaEventDisableTiming);
        cudaEventCreateWithFlags(&evGate, cudaEventDisableTiming);
    }
};
static StreamInit g_si;

__device__ __forceinline__ float elup1(float x) { return x > 0.f ? x + 1.f : __expf(x); }

__device__ __forceinline__ void tf32split(float v, float& hi, float& lo) {
    uint32_t u;
    asm("cvt.rna.tf32.f32 %0, %1;" : "=r"(u) : "f"(v));
    hi = __uint_as_float(u);
    float r = v - hi;
    uint32_t u2;
    asm("cvt.rna.tf32.f32 %0, %1;" : "=r"(u2) : "f"(r));
    lo = __uint_as_float(u2);
}

__device__ __forceinline__ void mma8(float* c, const uint32_t* a, const uint32_t* b) {
    asm volatile(
        "mma.sync.aligned.m16n8k8.row.col.f32.tf32.tf32.f32 "
        "{%0,%1,%2,%3},{%4,%5,%6,%7},{%8,%9},{%0,%1,%2,%3};"
        : "+f"(c[0]), "+f"(c[1]), "+f"(c[2]), "+f"(c[3])
        : "r"(a[0]), "r"(a[1]), "r"(a[2]), "r"(a[3]), "r"(b[0]), "r"(b[1]));
}

// ---------------- weight split prep (interleaved) ----------------
__global__ __launch_bounds__(256) void prep_split_k(
    const float* __restrict__ Wq, const float* __restrict__ Wa1,
    const float* __restrict__ Wg1, const float* __restrict__ Wg2,
    const float* __restrict__ Wg3, const float* __restrict__ Wo)
{
    const float* src; int off, len;
    switch (blockIdx.y) {
        case 0:  src = Wq;  off = OFF_Q;  len = 65536;  break;
        case 1:  src = Wa1; off = OFF_A1; len = 131072; break;
        case 2:  src = Wg1; off = OFF_G1; len = 16384;  break;
        case 3:  src = Wg2; off = OFF_G2; len = 36864;  break;
        case 4:  src = Wg3; off = OFF_G3; len = 16384;  break;
        default: src = Wo;  off = OFF_O;  len = 65536;  break;
    }
    for (int i = blockIdx.x * 256 + threadIdx.x; i < len; i += gridDim.x * 256) {
        float h, l;
        tf32split(src[i], h, l);
        *(float2*)&g_Wsp[2 * (size_t)(off + i)] = make_float2(h, l);
    }
}

// ---------------- tensor-core GEMM core ----------------
// M-tile 64; N-tile = NF*32. smem interleaved float2 {hi,lo} -> LDS.64 fragment loads.
// Y[b][o][n] = act( sum_k A[o][k]*X[b][k][n] + bias[o] ) * (mul? mul[b][o][n] : 1)
template<int ACT, bool CONV, int NF>
__device__ __forceinline__ void gemm_core(
    const float* __restrict__ Asp, const float* __restrict__ X,
    const float* __restrict__ bias, const float* __restrict__ mul,
    float* __restrict__ Y, int O, int K, int oby)
{
    constexpr int COLS = NF * 32;
    constexpr int BST  = COLS + 4;             // float2 stride
    extern __shared__ __align__(16) float sm[];
    float2* A2 = (float2*)sm;                  // [o][k], stride 36 float2
    float2* B2 = (float2*)(sm + 2 * 64 * 36);  // [k][n], stride BST float2

    const int tid = threadIdx.x;
    const int lane = tid & 31, warp = tid >> 5;
    const int wn = warp & 3, wm = warp >> 2;   // 2(m) x 4(n)
    const int obase = oby * 64, nbase = blockIdx.x * COLS, b = blockIdx.z;
    const int Cin = CONV ? (K / 9) : K;
    const float* Xb = X + (size_t)b * (size_t)Cin * NPIX;

    float acc[2][NF][4];
#pragma unroll
    for (int i = 0; i < 2; i++)
#pragma unroll
        for (int j = 0; j < NF; j++)
#pragma unroll
            for (int r = 0; r < 4; r++) acc[i][j][r] = 0.f;

    float4 pb[NF];
    if (!CONV) {
#pragma unroll
        for (int t = 0; t < NF; t++) {
            int i = tid + t * 256;
            int kk = i / (NF * 8), nq = i % (NF * 8);
            pb[t] = *(const float4*)&Xb[(size_t)kk * NPIX + nbase + nq * 4];
        }
    }

    for (int k0 = 0; k0 < K; k0 += 32) {
        // ---- stage A: 64 rows x 32 k interleaved = 1024 float4 chunks (2 k each) ----
#pragma unroll
        for (int t = 0; t < 4; t++) {
            int idx = tid + t * 256;
            int o = idx >> 4, kq = idx & 15;
            *(float4*)&sm[o * 72 + kq * 4] =
                *(const float4*)&Asp[2 * ((size_t)(obase + o) * K + k0 + kq * 2)];
        }
        // ---- stage B: split raw values (from prefetch regs) into interleaved pairs ----
        if (!CONV) {
#pragma unroll
            for (int t = 0; t < NF; t++) {
                int i = tid + t * 256;
                int kk = i / (NF * 8), nq = i % (NF * 8);
                float4 b4 = pb[t];
                float h0, l0, h1, l1, h2, l2, h3, l3;
                tf32split(b4.x, h0, l0); tf32split(b4.y, h1, l1);
                tf32split(b4.z, h2, l2); tf32split(b4.w, h3, l3);
                float* dst = (float*)&B2[kk * BST + nq * 4];
                *(float4*)dst       = make_float4(h0, l0, h1, l1);
                *(float4*)(dst + 4) = make_float4(h2, l2, h3, l3);
            }
        } else {
#pragma unroll
            for (int t = 0; t < NF * 4; t++) {
                int i = tid + t * 256;
                int kk = i / COLS, nn = i % COLS;
                int k = k0 + kk;
                int ic = k / 9, tp = k - ic * 9;
                int dy = tp / 3 - 1, dx = tp - (tp / 3) * 3 - 1;
                int n = nbase + nn;
                int y = n >> 6, x = n & 63;
                int yy = y + dy, xx = x + dx;
                float v = 0.f;
                if (yy >= 0 && yy < 64 && xx >= 0 && xx < 64)
                    v = Xb[(size_t)ic * NPIX + yy * 64 + xx];
                float h, l;
                tf32split(v, h, l);
                B2[kk * BST + nn] = make_float2(h, l);
            }
        }
        __syncthreads();

        // ---- prefetch next B tile (raw) ----
        if (!CONV && k0 + 32 < K) {
#pragma unroll
            for (int t = 0; t < NF; t++) {
                int i = tid + t * 256;
                int kk = i / (NF * 8), nq = i % (NF * 8);
                pb[t] = *(const float4*)&Xb[(size_t)(k0 + 32 + kk) * NPIX + nbase + nq * 4];
            }
        }

#pragma unroll
        for (int ks = 0; ks < 4; ks++) {
            const int kb = ks * 8 + (lane & 3);
            uint32_t bh[NF][2], bl[NF][2];
#pragma unroll
            for (int nf = 0; nf < NF; nf++) {
                int col = wn * (NF * 8) + nf * 8 + (lane >> 2);
                float2 t0 = B2[kb * BST + col];
                float2 t1 = B2[(kb + 4) * BST + col];
                bh[nf][0] = __float_as_uint(t0.x); bl[nf][0] = __float_as_uint(t0.y);
                bh[nf][1] = __float_as_uint(t1.x); bl[nf][1] = __float_as_uint(t1.y);
            }
#pragma unroll
            for (int mf = 0; mf < 2; mf++) {
                int row = wm * 32 + mf * 16 + (lane >> 2);
                float2 a0 = A2[row * 36 + kb];
                float2 a1 = A2[(row + 8) * 36 + kb];
                float2 a2 = A2[row * 36 + kb + 4];
                float2 a3 = A2[(row + 8) * 36 + kb + 4];
                uint32_t ah[4] = {__float_as_uint(a0.x), __float_as_uint(a1.x),
                                  __float_as_uint(a2.x), __float_as_uint(a3.x)};
                uint32_t al[4] = {__float_as_uint(a0.y), __float_as_uint(a1.y),
                                  __float_as_uint(a2.y), __float_as_uint(a3.y)};
#pragma unroll
                for (int nf = 0; nf < NF; nf++) {
                    mma8(acc[mf][nf], ah, bh[nf]);
                    mma8(acc[mf][nf], ah, bl[nf]);
                    mma8(acc[mf][nf], al, bh[nf]);
                }
            }
        }
        __syncthreads();
    }

    // ---- epilogue ----
#pragma unroll
    for (int mf = 0; mf < 2; mf++) {
        int o0 = obase + wm * 32 + mf * 16 + (lane >> 2);
        int o1 = o0 + 8;
        float bi0 = bias ? bias[o0] : 0.f;
        float bi1 = bias ? bias[o1] : 0.f;
        size_t r0 = ((size_t)b * O + o0) * NPIX;
        size_t r1 = ((size_t)b * O + o1) * NPIX;
#pragma unroll
        for (int nf = 0; nf < NF; nf++) {
            int n = nbase + wn * (NF * 8) + nf * 8 + 2 * (lane & 3);
            float v00 = acc[mf][nf][0] + bi0, v01 = acc[mf][nf][1] + bi0;
            float v10 = acc[mf][nf][2] + bi1, v11 = acc[mf][nf][3] + bi1;
            if (ACT == 1) {
                v00 = v00 > 0.f ? v00 : 0.2f * v00; v01 = v01 > 0.f ? v01 : 0.2f * v01;
                v10 = v10 > 0.f ? v10 : 0.2f * v10; v11 = v11 > 0.f ? v11 : 0.2f * v11;
            }
            if (ACT == 2) { v00 = elup1(v00); v01 = elup1(v01); v10 = elup1(v10); v11 = elup1(v11); }
            if (mul) {
                v00 *= mul[r0 + n]; v01 *= mul[r0 + n + 1];
                v10 *= mul[r1 + n]; v11 *= mul[r1 + n + 1];
            }
            *(float2*)&Y[r0 + n] = make_float2(v00, v01);
            *(float2*)&Y[r1 + n] = make_float2(v10, v11);
        }
    }
}

template<int ACT, bool CONV, int NF>
__global__ __launch_bounds__(256, 2) void gemm_tc(
    const float* __restrict__ Asp, const float* __restrict__ X,
    const float* __restrict__ bias, const float* __restrict__ mul,
    float* __restrict__ Y, int O, int K)
{
    gemm_core<ACT, CONV, NF>(Asp, X, bias, mul, Y, O, K, blockIdx.y);
}

// ---------------- depthwise 3x3 SAME ----------------
__global__ __launch_bounds__(256) void dwconv_k(const float* __restrict__ W)
{
    __shared__ float sp[66][68];
    int c = blockIdx.x & 511, b = blockIdx.x >> 9;
    const float* Xc = g_kv + ((size_t)(b * 512 + c)) * NPIX;
    float* Oc = g_kvdw + ((size_t)(b * 512 + c)) * NPIX;

    for (int i = threadIdx.x; i < 66 * 66; i += 256) {
        int r = i / 66, col = i - r * 66;
        int y = r - 1, x = col - 1;
        sp[r][col] = (y >= 0 && y < 64 && x >= 0 && x < 64) ? Xc[y * 64 + x] : 0.f;
    }
    float w[9];
#pragma unroll
    for (int j = 0; j < 9; j++) w[j] = W[c * 9 + j];
    __syncthreads();

    bool isk = (c < 256);
    for (int i = threadIdx.x; i < 4096; i += 256) {
        int y = i >> 6, x = i & 63;
        float acc = 0.f;
#pragma unroll
        for (int dy = 0; dy < 3; dy++)
#pragma unroll
            for (int dx = 0; dx < 3; dx++)
                acc += w[dy * 3 + dx] * sp[y + dy][x + dx];
        Oc[i] = isk ? elup1(acc) : acc;
    }
}

// ---------------- attention phase 1 ----------------
__global__ __launch_bounds__(256) void attn_chunk_sums_k()
{
    __shared__ __align__(16) float sk[64 * 68];
    __shared__ __align__(16) float sv[64 * 68];
    __shared__ float sred[256];

    int tid = threadIdx.x;
    int ch = blockIdx.x, h = blockIdx.y, b = blockIdx.z;
    bool rev = (h >= 2);
    int base = ch * 64;
    int bh = b * NHEAD + h;

    for (int i = tid; i < 4096; i += 256) {
        int d = i >> 6, nn = i & 63;
        int p = rev ? (NPIX - 1 - (base + nn)) : (base + nn);
        size_t off = ((size_t)b * 512 + h * 64 + d) * NPIX + p;
        sk[nn * 68 + d] = g_kvdw[off];
        sv[nn * 68 + d] = g_kvdw[off + (size_t)256 * NPIX];
    }
    __syncthreads();

    int e0 = (tid & 15) * 4, d0 = (tid >> 4) * 4;
    float acc[4][4];
#pragma unroll
    for (int i = 0; i < 4; i++)
#pragma unroll
        for (int j = 0; j < 4; j++) acc[i][j] = 0.f;

    for (int nn = 0; nn < 64; nn++) {
        float4 k4 = *(const float4*)&sk[nn * 68 + d0];
        float4 v4 = *(const float4*)&sv[nn * 68 + e0];
        float kv[4] = {k4.x, k4.y, k4.z, k4.w};
        float vv[4] = {v4.x, v4.y, v4.z, v4.w};
#pragma unroll
        for (int i = 0; i < 4; i++)
#pragma unroll
            for (int j = 0; j < 4; j++) acc[i][j] += kv[i] * vv[j];
    }
    {
        int d = tid & 63, g = tid >> 6;
        float part = 0.f;
#pragma unroll
        for (int t = 0; t < 16; t++) part += sk[(g * 16 + t) * 68 + d];
        sred[g * 64 + d] = part;
    }
    __syncthreads();
#pragma unroll
    for (int i = 0; i < 4; i++)
#pragma unroll
        for (int j = 0; j < 4; j++) sk[(d0 + i) * 68 + (e0 + j)] = acc[i][j];
    __syncthreads();

    float* Sg = g_S + ((size_t)(bh * NCHUNK + ch)) * 4096;
    for (int i = tid; i < 4096; i += 256) Sg[i] = sk[(i >> 6) * 68 + (i & 63)];
    if (tid < 64) {
        float s = sred[tid] + sred[64 + tid] + sred[128 + tid] + sred[192 + tid];
        g_ksum[(bh * NCHUNK + ch) * 64 + tid] = s;
    }
}

// ---------------- attention phase 2 ----------------
__global__ __launch_bounds__(256) void attn_prefix_k()
{
    int bh = blockIdx.y;
    int e = blockIdx.x * 256 + threadIdx.x;
    float* Sg = g_S + (size_t)bh * NCHUNK * 4096;
    float run = 0.f;
#pragma unroll 4
    for (int c = 0; c < NCHUNK; c++) {
        float v = Sg[(size_t)c * 4096 + e];
        Sg[(size_t)c * 4096 + e] = run;
        run += v;
    }
    if (blockIdx.x == 0 && threadIdx.x < 64) {
        int d = threadIdx.x;
        float r2 = 0.f;
        for (int c = 0; c < NCHUNK; c++) {
            float v = g_ksum[(bh * NCHUNK + c) * 64 + d];
            g_ksum[(bh * NCHUNK + c) * 64 + d] = r2;
            r2 += v;
        }
    }
}

// ---------------- attention phase 3 ----------------
#define P3_SMEM_FLOATS (4 * 64 * 68 + 64 + 64 + 256)
__global__ __launch_bounds__(256) void attn_out_k()
{
    extern __shared__ __align__(16) float sm[];
    float* sqT = sm;
    float* skv = sm + 4352;
    float* sAT = sm + 8704;
    float* sS  = sm + 13056;
    float* sks   = sm + 17408;
    float* srden = sm + 17472;
    float* sred  = sm + 17536;

    int tid = threadIdx.x;
    int ch = blockIdx.x, h = blockIdx.y, b = blockIdx.z;
    bool rev = (h >= 2);
    int base = ch * 64;
    int bh = b * NHEAD + h;

    for (int i = tid; i < 4096; i += 256) {
        int d = i >> 6, nn = i & 63;
        int p = rev ? (NPIX - 1 - (base + nn)) : (base + nn);
        sqT[d * 68 + nn] = g_q[((size_t)b * 256 + h * 64 + d) * NPIX + p];
        skv[d * 68 + nn] = g_kvdw[((size_t)b * 512 + h * 64 + d) * NPIX + p];
    }
    {
        const float* Sg = g_S + ((size_t)(bh * NCHUNK + ch)) * 4096;
        for (int i = tid; i < 4096; i += 256) sS[(i >> 6) * 68 + (i & 63)] = Sg[i];
    }
    if (tid < 64) sks[tid] = g_ksum[(bh * NCHUNK + ch) * 64 + tid];
    __syncthreads();

    {
        int n0 = (tid & 15) * 4, m0 = (tid >> 4) * 4;
        float a[4][4];
#pragma unroll
        for (int i = 0; i < 4; i++)
#pragma unroll
            for (int j = 0; j < 4; j++) a[i][j] = 0.f;
        for (int d = 0; d < 64; d++) {
            float4 q4 = *(const float4*)&sqT[d * 68 + n0];
            float4 k4 = *(const float4*)&skv[d * 68 + m0];
            float kv[4] = {k4.x, k4.y, k4.z, k4.w};
            float qv[4] = {q4.x, q4.y, q4.z, q4.w};
#pragma unroll
            for (int i = 0; i < 4; i++)
#pragma unroll
                for (int j = 0; j < 4; j++) a[i][j] += kv[i] * qv[j];
        }
        __syncthreads();
#pragma unroll
        for (int i = 0; i < 4; i++)
#pragma unroll
            for (int j = 0; j < 4; j++)
                sAT[(m0 + i) * 68 + (n0 + j)] = (m0 + i <= n0 + j) ? a[i][j] : 0.f;
    }
    for (int i = tid; i < 4096; i += 256) {
        int e = i >> 6, mm = i & 63;
        int p = rev ? (NPIX - 1 - (base + mm)) : (base + mm);
        skv[mm * 68 + e] = g_kvdw[((size_t)b * 512 + 256 + h * 64 + e) * NPIX + p];
    }
    __syncthreads();
    {
        int n = tid & 63, g = tid >> 6;
        float part = 0.f;
#pragma unroll
        for (int t = 0; t < 16; t++) {
            int m = g * 16 + t;
            part += sAT[m * 68 + n] + sqT[m * 68 + n] * sks[m];
        }
        sred[g * 64 + n] = part;
    }
    __syncthreads();

    int n0 = (tid & 15) * 4, e0 = (tid >> 4) * 4;
    float acc[4][4];
#pragma unroll
    for (int i = 0; i < 4; i++)
#pragma unroll
        for (int j = 0; j < 4; j++) acc[i][j] = 0.f;
    for (int m = 0; m < 64; m++) {
        float4 a4 = *(const float4*)&sAT[m * 68 + n0];
        float4 v4 = *(const float4*)&skv[m * 68 + e0];
        float vv[4] = {v4.x, v4.y, v4.z, v4.w};
        float av[4] = {a4.x, a4.y, a4.z, a4.w};
#pragma unroll
        for (int i = 0; i < 4; i++)
#pragma unroll
            for (int j = 0; j < 4; j++) acc[i][j] += vv[i] * av[j];
    }
    for (int d = 0; d < 64; d++) {
        float4 q4 = *(const float4*)&sqT[d * 68 + n0];
        float4 s4 = *(const float4*)&sS[d * 68 + e0];
        float sv4[4] = {s4.x, s4.y, s4.z, s4.w};
        float qv[4] = {q4.x, q4.y, q4.z, q4.w};
#pragma unroll
        for (int i = 0; i < 4; i++)
#pragma unroll
            for (int j = 0; j < 4; j++) acc[i][j] += sv4[i] * qv[j];
    }
    __syncthreads();
#pragma unroll
    for (int i = 0; i < 4; i++)
#pragma unroll
        for (int j = 0; j < 4; j++) sAT[(e0 + i) * 68 + (n0 + j)] = acc[i][j];
    if (tid < 64)
        srden[tid] = 1.f / (1e-6f + sred[tid] + sred[64 + tid] + sred[128 + tid] + sred[192 + tid]);
    __syncthreads();

    for (int i = tid; i < 4096; i += 256) {
        int e = i >> 6, nn = i & 63;
        int p = rev ? (NPIX - 1 - (base + nn)) : (base + nn);
        g_attn[((size_t)b * 256 + h * 64 + e) * NPIX + p] = sAT[e * 68 + nn] * srden[nn];
    }
}

// ---------------- launch ----------------
#define SMEM_TC4 ((2 * 64 * 36 + 2 * 32 * 132) * 4)
#define SMEM_TC2 ((2 * 64 * 36 + 2 * 32 * 68) * 4)

extern "C" void kernel_launch(void* const* d_in, const int* in_sizes, int n_in,
                              void* d_out, int out_size)
{
    (void)in_sizes; (void)n_in; (void)out_size;
    const float* x   = (const float*)d_in[0];
    const float* Wq  = (const float*)d_in[1];
    const float* bq  = (const float*)d_in[2];
    const float* Wa1 = (const float*)d_in[3];
    const float* Wdw = (const float*)d_in[4];
    const float* Wo  = (const float*)d_in[5];
    const float* bo  = (const float*)d_in[6];
    const float* Wg1 = (const float*)d_in[7];
    const float* bg1 = (const float*)d_in[8];
    const float* Wg2 = (const float*)d_in[9];
    const float* bg2 = (const float*)d_in[10];
    const float* Wg3 = (const float*)d_in[11];
    const float* bg3 = (const float*)d_in[12];
    float* out = (float*)d_out;

    float *qb, *kvb, *attnb, *g1b, *g2b, *gatedb, *wsp;
    cudaGetSymbolAddress((void**)&qb,    g_q);
    cudaGetSymbolAddress((void**)&kvb,   g_kv);
    cudaGetSymbolAddress((void**)&attnb, g_attn);
    cudaGetSymbolAddress((void**)&g1b,   g_g1);
    cudaGetSymbolAddress((void**)&g2b,   g_g2);
    cudaGetSymbolAddress((void**)&gatedb,g_gated);
    cudaGetSymbolAddress((void**)&wsp,   g_Wsp);

    cudaFuncSetAttribute(gemm_tc<0, false, 4>, cudaFuncAttributeMaxDynamicSharedMemorySize, SMEM_TC4);
    cudaFuncSetAttribute(gemm_tc<2, false, 4>, cudaFuncAttributeMaxDynamicSharedMemorySize, SMEM_TC4);
    cudaFuncSetAttribute(gemm_tc<1, false, 2>, cudaFuncAttributeMaxDynamicSharedMemorySize, SMEM_TC2);
    cudaFuncSetAttribute(gemm_tc<1, true,  2>, cudaFuncAttributeMaxDynamicSharedMemorySize, SMEM_TC2);
    cudaFuncSetAttribute(attn_out_k, cudaFuncAttributeMaxDynamicSharedMemorySize, P3_SMEM_FLOATS * 4);

    dim3 blk(256);
    cudaStream_t s0 = 0, s1 = g_si.s1;

    // weights split
    prep_split_k<<<dim3(512, 6), blk, 0, s0>>>(Wq, Wa1, Wg1, Wg2, Wg3, Wo);
    cudaEventRecord(g_si.evFork, s0);

    // ---- side stream: q, then gate chain g1 -> g2 ----
    cudaStreamWaitEvent(s1, g_si.evFork, 0);
    gemm_tc<2, false, 4><<<dim3(32, 4, 2), blk, SMEM_TC4, s1>>>(wsp + 2 * OFF_Q, x, bq, nullptr, qb, 256, 256);
    cudaEventRecord(g_si.evQ, s1);
    gemm_tc<1, false, 2><<<dim3(64, 1, 2), blk, SMEM_TC2, s1>>>(wsp + 2 * OFF_G1, x, bg1, nullptr, g1b, 64, 256);
    gemm_tc<1, true,  2><<<dim3(64, 1, 2), blk, SMEM_TC2, s1>>>(wsp + 2 * OFF_G2, g1b, bg2, nullptr, g2b, 64, 576);
    cudaEventRecord(g_si.evGate, s1);

    // ---- main stream: kv -> dwconv -> attention ----
    gemm_tc<0, false, 4><<<dim3(32, 8, 2), blk, SMEM_TC4, s0>>>(wsp + 2 * OFF_A1, x, nullptr, nullptr, kvb, 512, 256);
    dwconv_k<<<BATCH * 512, blk, 0, s0>>>(Wdw);
    attn_chunk_sums_k<<<dim3(NCHUNK, NHEAD, BATCH), blk, 0, s0>>>();
    attn_prefix_k<<<dim3(16, BATCH * NHEAD), blk, 0, s0>>>();
    cudaStreamWaitEvent(s0, g_si.evQ, 0);          // attn_out needs q
    attn_out_k<<<dim3(NCHUNK, NHEAD, BATCH), blk, P3_SMEM_FLOATS * 4, s0>>>();

    // ---- tail: gated = (Wg3@g2 + bg3) * attn ; out = Wo@gated + bo ----
    cudaStreamWaitEvent(s0, g_si.evGate, 0);
    gemm_tc<0, false, 4><<<dim3(32, 4, 2), blk, SMEM_TC4, s0>>>(wsp + 2 * OFF_G3, g2b, bg3, attnb, gatedb, 256, 64);
    gemm_tc<0, false, 4><<<dim3(32, 4, 2), blk, SMEM_TC4, s0>>>(wsp + 2 * OFF_O, gatedb, bo, nullptr, out, 256, 256);
}

// round 14
// speedup vs baseline: 1.1059x; 1.1059x over previous
#include <cuda_runtime.h>
#include <cstdint>
#include <cstddef>

#define BATCH 2
#define CCH   256
#define NPIX  4096
#define NHEAD 4
#define DDIM  64
#define NCHUNK 64

// ---------------- scratch ----------------
__device__ float g_q    [BATCH * CCH     * NPIX];
__device__ float g_kv   [BATCH * 2*CCH   * NPIX];
__device__ float g_kvdw [BATCH * 2*CCH   * NPIX];
__device__ float g_attn [BATCH * CCH     * NPIX];
__device__ float g_g1   [BATCH * 64      * NPIX];
__device__ float g_g2   [BATCH * 64      * NPIX];
__device__ float g_gated[BATCH * CCH     * NPIX];
__device__ float g_S    [BATCH * NHEAD * NCHUNK * DDIM * DDIM];
__device__ float g_ksum [BATCH * NHEAD * NCHUNK * DDIM];

// pre-split weights (hi/lo tf32, separate arrays)
#define OFF_Q  0
#define OFF_A1 65536
#define OFF_G1 196608
#define OFF_G2 212992
#define OFF_G3 249856
#define OFF_O  266240
#define W_TOTAL 331776
__device__ float g_Whi[W_TOTAL];
__device__ float g_Wlo[W_TOTAL];

// ---------------- streams/events (created at load, outside kernel_launch) ----------
struct StreamInit {
    cudaStream_t s1;
    cudaEvent_t evFork, evQ, evGate;
    StreamInit() {
        cudaStreamCreateWithFlags(&s1, cudaStreamNonBlocking);
        cudaEventCreateWithFlags(&evFork, cudaEventDisableTiming);
        cudaEventCreateWithFlags(&evQ,    cudaEventDisableTiming);
        cudaEventCreateWithFlags(&evGate, cudaEventDisableTiming);
    }
};
static StreamInit g_si;

__device__ __forceinline__ float elup1(float x) { return x > 0.f ? x + 1.f : __expf(x); }

__device__ __forceinline__ void tf32split(float v, float& hi, float& lo) {
    uint32_t u;
    asm("cvt.rna.tf32.f32 %0, %1;" : "=r"(u) : "f"(v));
    hi = __uint_as_float(u);
    float r = v - hi;
    uint32_t u2;
    asm("cvt.rna.tf32.f32 %0, %1;" : "=r"(u2) : "f"(r));
    lo = __uint_as_float(u2);
}

__device__ __forceinline__ void mma8(float* c, const uint32_t* a, const uint32_t* b) {
    asm volatile(
        "mma.sync.aligned.m16n8k8.row.col.f32.tf32.tf32.f32 "
        "{%0,%1,%2,%3},{%4,%5,%6,%7},{%8,%9},{%0,%1,%2,%3};"
        : "+f"(c[0]), "+f"(c[1]), "+f"(c[2]), "+f"(c[3])
        : "r"(a[0]), "r"(a[1]), "r"(a[2]), "r"(a[3]), "r"(b[0]), "r"(b[1]));
}

// ---------------- weight split prep ----------------
__global__ __launch_bounds__(256) void prep_split_k(
    const float* __restrict__ Wq, const float* __restrict__ Wa1,
    const float* __restrict__ Wg1, const float* __restrict__ Wg2,
    const float* __restrict__ Wg3, const float* __restrict__ Wo)
{
    const float* src; int off, len;
    switch (blockIdx.y) {
        case 0:  src = Wq;  off = OFF_Q;  len = 65536;  break;
        case 1:  src = Wa1; off = OFF_A1; len = 131072; break;
        case 2:  src = Wg1; off = OFF_G1; len = 16384;  break;
        case 3:  src = Wg2; off = OFF_G2; len = 36864;  break;
        case 4:  src = Wg3; off = OFF_G3; len = 16384;  break;
        default: src = Wo;  off = OFF_O;  len = 65536;  break;
    }
    for (int i = blockIdx.x * 256 + threadIdx.x; i < len; i += gridDim.x * 256) {
        float h, l;
        tf32split(src[i], h, l);
        g_Whi[off + i] = h;
        g_Wlo[off + i] = l;
    }
}

// ---------------- tensor-core GEMM core (round-10 proven version) ----------------
template<int ACT, bool CONV, int NF>
__device__ __forceinline__ void gemm_core(
    const float* __restrict__ Ahi, const float* __restrict__ Alo,
    const float* __restrict__ X,
    const float* __restrict__ bias, const float* __restrict__ mul,
    float* __restrict__ Y, int O, int K, int oby)
{
    constexpr int COLS = NF * 32;
    constexpr int BST  = COLS + 4;
    extern __shared__ __align__(16) float sm[];
    float* Ah = sm;                        // 64 x 36
    float* Al = Ah + 64 * 36;
    float* Bh = Al + 64 * 36;              // 32 x BST
    float* Bl = Bh + 32 * BST;

    const int tid = threadIdx.x;
    const int lane = tid & 31, warp = tid >> 5;
    const int wn = warp & 3, wm = warp >> 2;
    const int obase = oby * 64, nbase = blockIdx.x * COLS, b = blockIdx.z;
    const int Cin = CONV ? (K / 9) : K;
    const float* Xb = X + (size_t)b * (size_t)Cin * NPIX;

    float acc[2][NF][4];
#pragma unroll
    for (int i = 0; i < 2; i++)
#pragma unroll
        for (int j = 0; j < NF; j++)
#pragma unroll
            for (int r = 0; r < 4; r++) acc[i][j][r] = 0.f;

    float4 pb[NF];
    if (!CONV) {
#pragma unroll
        for (int t = 0; t < NF; t++) {
            int i = tid + t * 256;
            int kk = i / (NF * 8), nq = i % (NF * 8);
            pb[t] = *(const float4*)&Xb[(size_t)kk * NPIX + nbase + nq * 4];
        }
    }

    for (int k0 = 0; k0 < K; k0 += 32) {
        // ---- stage A (pre-split copy) ----
#pragma unroll
        for (int t = 0; t < 2; t++) {
            int ii = tid + t * 256;
            int oo = ii >> 3, kq2 = ii & 7;
            size_t gi = (size_t)(obase + oo) * K + k0 + kq2 * 4;
            *(float4*)&Ah[oo * 36 + kq2 * 4] = *(const float4*)&Ahi[gi];
            *(float4*)&Al[oo * 36 + kq2 * 4] = *(const float4*)&Alo[gi];
        }
        // ---- stage B ----
        if (!CONV) {
#pragma unroll
            for (int t = 0; t < NF; t++) {
                int i = tid + t * 256;
                int kk = i / (NF * 8), nq = i % (NF * 8);
                float4 b4 = pb[t];
                float4 h4, l4;
                tf32split(b4.x, h4.x, l4.x); tf32split(b4.y, h4.y, l4.y);
                tf32split(b4.z, h4.z, l4.z); tf32split(b4.w, h4.w, l4.w);
                *(float4*)&Bh[kk * BST + nq * 4] = h4;
                *(float4*)&Bl[kk * BST + nq * 4] = l4;
            }
        } else {
#pragma unroll
            for (int t = 0; t < NF * 4; t++) {
                int i = tid + t * 256;
                int kk = i / COLS, nn = i % COLS;
                int k = k0 + kk;
                int ic = k / 9, tp = k - ic * 9;
                int dy = tp / 3 - 1, dx = tp - (tp / 3) * 3 - 1;
                int n = nbase + nn;
                int y = n >> 6, x = n & 63;
                int yy = y + dy, xx = x + dx;
                float v = 0.f;
                if (yy >= 0 && yy < 64 && xx >= 0 && xx < 64)
                    v = Xb[(size_t)ic * NPIX + yy * 64 + xx];
                float h, l;
                tf32split(v, h, l);
                Bh[kk * BST + nn] = h;
                Bl[kk * BST + nn] = l;
            }
        }
        __syncthreads();

        if (!CONV && k0 + 32 < K) {
#pragma unroll
            for (int t = 0; t < NF; t++) {
                int i = tid + t * 256;
                int kk = i / (NF * 8), nq = i % (NF * 8);
                pb[t] = *(const float4*)&Xb[(size_t)(k0 + 32 + kk) * NPIX + nbase + nq * 4];
            }
        }

#pragma unroll
        for (int ks = 0; ks < 4; ks++) {
            const int kb = ks * 8 + (lane & 3);
            uint32_t bh[NF][2], bl[NF][2];
#pragma unroll
            for (int nf = 0; nf < NF; nf++) {
                int col = wn * (NF * 8) + nf * 8 + (lane >> 2);
                bh[nf][0] = __float_as_uint(Bh[kb * BST + col]);
                bh[nf][1] = __float_as_uint(Bh[(kb + 4) * BST + col]);
                bl[nf][0] = __float_as_uint(Bl[kb * BST + col]);
                bl[nf][1] = __float_as_uint(Bl[(kb + 4) * BST + col]);
            }
#pragma unroll
            for (int mf = 0; mf < 2; mf++) {
                int row = wm * 32 + mf * 16 + (lane >> 2);
                uint32_t ah[4], al[4];
                ah[0] = __float_as_uint(Ah[row * 36 + kb]);
                ah[1] = __float_as_uint(Ah[(row + 8) * 36 + kb]);
                ah[2] = __float_as_uint(Ah[row * 36 + kb + 4]);
                ah[3] = __float_as_uint(Ah[(row + 8) * 36 + kb + 4]);
                al[0] = __float_as_uint(Al[row * 36 + kb]);
                al[1] = __float_as_uint(Al[(row + 8) * 36 + kb]);
                al[2] = __float_as_uint(Al[row * 36 + kb + 4]);
                al[3] = __float_as_uint(Al[(row + 8) * 36 + kb + 4]);
#pragma unroll
                for (int nf = 0; nf < NF; nf++) {
                    mma8(acc[mf][nf], ah, bh[nf]);
                    mma8(acc[mf][nf], ah, bl[nf]);
                    mma8(acc[mf][nf], al, bh[nf]);
                }
            }
        }
        __syncthreads();
    }

    // ---- epilogue ----
#pragma unroll
    for (int mf = 0; mf < 2; mf++) {
        int o0 = obase + wm * 32 + mf * 16 + (lane >> 2);
        int o1 = o0 + 8;
        float bi0 = bias ? bias[o0] : 0.f;
        float bi1 = bias ? bias[o1] : 0.f;
        size_t r0 = ((size_t)b * O + o0) * NPIX;
        size_t r1 = ((size_t)b * O + o1) * NPIX;
#pragma unroll
        for (int nf = 0; nf < NF; nf++) {
            int n = nbase + wn * (NF * 8) + nf * 8 + 2 * (lane & 3);
            float v00 = acc[mf][nf][0] + bi0, v01 = acc[mf][nf][1] + bi0;
            float v10 = acc[mf][nf][2] + bi1, v11 = acc[mf][nf][3] + bi1;
            if (ACT == 1) {
                v00 = v00 > 0.f ? v00 : 0.2f * v00; v01 = v01 > 0.f ? v01 : 0.2f * v01;
                v10 = v10 > 0.f ? v10 : 0.2f * v10; v11 = v11 > 0.f ? v11 : 0.2f * v11;
            }
            if (ACT == 2) { v00 = elup1(v00); v01 = elup1(v01); v10 = elup1(v10); v11 = elup1(v11); }
            if (mul) {
                v00 *= mul[r0 + n]; v01 *= mul[r0 + n + 1];
                v10 *= mul[r1 + n]; v11 *= mul[r1 + n + 1];
            }
            *(float2*)&Y[r0 + n] = make_float2(v00, v01);
            *(float2*)&Y[r1 + n] = make_float2(v10, v11);
        }
    }
}

template<int ACT, bool CONV, int NF>
__global__ __launch_bounds__(256, 2) void gemm_tc(
    const float* __restrict__ Ahi, const float* __restrict__ Alo,
    const float* __restrict__ X,
    const float* __restrict__ bias, const float* __restrict__ mul,
    float* __restrict__ Y, int O, int K)
{
    gemm_core<ACT, CONV, NF>(Ahi, Alo, X, bias, mul, Y, O, K, blockIdx.y);
}

// ---------------- depthwise 3x3 SAME ----------------
__global__ __launch_bounds__(256) void dwconv_k(const float* __restrict__ W)
{
    __shared__ float sp[66][68];
    int c = blockIdx.x & 511, b = blockIdx.x >> 9;
    const float* Xc = g_kv + ((size_t)(b * 512 + c)) * NPIX;
    float* Oc = g_kvdw + ((size_t)(b * 512 + c)) * NPIX;

    for (int i = threadIdx.x; i < 66 * 66; i += 256) {
        int r = i / 66, col = i - r * 66;
        int y = r - 1, x = col - 1;
        sp[r][col] = (y >= 0 && y < 64 && x >= 0 && x < 64) ? Xc[y * 64 + x] : 0.f;
    }
    float w[9];
#pragma unroll
    for (int j = 0; j < 9; j++) w[j] = W[c * 9 + j];
    __syncthreads();

    bool isk = (c < 256);
    for (int i = threadIdx.x; i < 4096; i += 256) {
        int y = i >> 6, x = i & 63;
        float acc = 0.f;
#pragma unroll
        for (int dy = 0; dy < 3; dy++)
#pragma unroll
            for (int dx = 0; dx < 3; dx++)
                acc += w[dy * 3 + dx] * sp[y + dy][x + dx];
        Oc[i] = isk ? elup1(acc) : acc;
    }
}

// ---------------- attention phase 1 (TENSOR CORE): S_c = k^T v, ksum_c -------------
// A = k transposed [d][n] (M=64, K=64), B = v [n][e] (N=64). Same fragment maps as gemm_tc.
#define P1_SMEM_FLOATS (4 * 64 * 68 + 256)
__global__ __launch_bounds__(256, 2) void attn_chunk_sums_tc()
{
    extern __shared__ __align__(16) float sm[];
    float* Ah = sm;                 // [d][n] stride 68
    float* Al = Ah + 64 * 68;
    float* Bh = Al + 64 * 68;       // [n][e] stride 68
    float* Bl = Bh + 64 * 68;
    float* sred = Bl + 64 * 68;     // 256

    const int tid = threadIdx.x;
    const int lane = tid & 31, warp = tid >> 5;
    const int wn = warp & 3, wm = warp >> 2;
    int ch = blockIdx.x, h = blockIdx.y, b = blockIdx.z;
    bool rev = (h >= 2);
    int base = ch * 64;
    int bh_idx = b * NHEAD + h;

    for (int i = tid; i < 4096; i += 256) {
        int d = i >> 6, nn = i & 63;
        int p = rev ? (NPIX - 1 - (base + nn)) : (base + nn);
        size_t off = ((size_t)b * 512 + h * 64 + d) * NPIX + p;
        float kvk = g_kvdw[off];                       // elup1'd already
        float kvv = g_kvdw[off + (size_t)256 * NPIX];
        float hh, ll;
        tf32split(kvk, hh, ll);
        Ah[d * 68 + nn] = hh; Al[d * 68 + nn] = ll;    // A[d][n] = k[n][d]
        tf32split(kvv, hh, ll);
        Bh[nn * 68 + d] = hh; Bl[nn * 68 + d] = ll;    // B[n][e] = v[n][e]
    }
    __syncthreads();

    float acc[2][2][4];
#pragma unroll
    for (int i = 0; i < 2; i++)
#pragma unroll
        for (int j = 0; j < 2; j++)
#pragma unroll
            for (int r = 0; r < 4; r++) acc[i][j][r] = 0.f;

#pragma unroll
    for (int ks = 0; ks < 8; ks++) {
        const int kb = ks * 8 + (lane & 3);
        uint32_t bh2[2][2], bl2[2][2];
#pragma unroll
        for (int nf = 0; nf < 2; nf++) {
            int col = wn * 16 + nf * 8 + (lane >> 2);
            bh2[nf][0] = __float_as_uint(Bh[kb * 68 + col]);
            bh2[nf][1] = __float_as_uint(Bh[(kb + 4) * 68 + col]);
            bl2[nf][0] = __float_as_uint(Bl[kb * 68 + col]);
            bl2[nf][1] = __float_as_uint(Bl[(kb + 4) * 68 + col]);
        }
#pragma unroll
        for (int mf = 0; mf < 2; mf++) {
            int row = wm * 32 + mf * 16 + (lane >> 2);
            uint32_t ah[4], al[4];
            ah[0] = __float_as_uint(Ah[row * 68 + kb]);
            ah[1] = __float_as_uint(Ah[(row + 8) * 68 + kb]);
            ah[2] = __float_as_uint(Ah[row * 68 + kb + 4]);
            ah[3] = __float_as_uint(Ah[(row + 8) * 68 + kb + 4]);
            al[0] = __float_as_uint(Al[row * 68 + kb]);
            al[1] = __float_as_uint(Al[(row + 8) * 68 + kb]);
            al[2] = __float_as_uint(Al[row * 68 + kb + 4]);
            al[3] = __float_as_uint(Al[(row + 8) * 68 + kb + 4]);
#pragma unroll
            for (int nf = 0; nf < 2; nf++) {
                mma8(acc[mf][nf], ah, bh2[nf]);
                mma8(acc[mf][nf], ah, bl2[nf]);
                mma8(acc[mf][nf], al, bh2[nf]);
            }
        }
    }

    // write S directly from accumulator fragments
    float* Sg = g_S + ((size_t)(bh_idx * NCHUNK + ch)) * 4096;
#pragma unroll
    for (int mf = 0; mf < 2; mf++) {
        int d0 = wm * 32 + mf * 16 + (lane >> 2);
        int d1 = d0 + 8;
#pragma unroll
        for (int nf = 0; nf < 2; nf++) {
            int e = wn * 16 + nf * 8 + 2 * (lane & 3);
            *(float2*)&Sg[d0 * 64 + e] = make_float2(acc[mf][nf][0], acc[mf][nf][1]);
            *(float2*)&Sg[d1 * 64 + e] = make_float2(acc[mf][nf][2], acc[mf][nf][3]);
        }
    }

    // ksum[d] = sum_n k[n][d] = row-sum of (Ah + Al)
    {
        int d = tid & 63, g = tid >> 6;
        float part = 0.f;
#pragma unroll
        for (int t = 0; t < 16; t++) {
            int nn = g * 16 + t;
            part += Ah[d * 68 + nn] + Al[d * 68 + nn];
        }
        sred[g * 64 + d] = part;
    }
    __syncthreads();
    if (tid < 64)
        g_ksum[(bh_idx * NCHUNK + ch) * 64 + tid] =
            sred[tid] + sred[64 + tid] + sred[128 + tid] + sred[192 + tid];
}

// ---------------- attention phase 2 ----------------
__global__ __launch_bounds__(256) void attn_prefix_k()
{
    int bh = blockIdx.y;
    int e = blockIdx.x * 256 + threadIdx.x;
    float* Sg = g_S + (size_t)bh * NCHUNK * 4096;
    float run = 0.f;
#pragma unroll 4
    for (int c = 0; c < NCHUNK; c++) {
        float v = Sg[(size_t)c * 4096 + e];
        Sg[(size_t)c * 4096 + e] = run;
        run += v;
    }
    if (blockIdx.x == 0 && threadIdx.x < 64) {
        int d = threadIdx.x;
        float r2 = 0.f;
        for (int c = 0; c < NCHUNK; c++) {
            float v = g_ksum[(bh * NCHUNK + c) * 64 + d];
            g_ksum[(bh * NCHUNK + c) * 64 + d] = r2;
            r2 += v;
        }
    }
}

// ---------------- attention phase 3 ----------------
#define P3_SMEM_FLOATS (4 * 64 * 68 + 64 + 64 + 256)
__global__ __launch_bounds__(256) void attn_out_k()
{
    extern __shared__ __align__(16) float sm[];
    float* sqT = sm;
    float* skv = sm + 4352;
    float* sAT = sm + 8704;
    float* sS  = sm + 13056;
    float* sks   = sm + 17408;
    float* srden = sm + 17472;
    float* sred  = sm + 17536;

    int tid = threadIdx.x;
    int ch = blockIdx.x, h = blockIdx.y, b = blockIdx.z;
    bool rev = (h >= 2);
    int base = ch * 64;
    int bh = b * NHEAD + h;

    for (int i = tid; i < 4096; i += 256) {
        int d = i >> 6, nn = i & 63;
        int p = rev ? (NPIX - 1 - (base + nn)) : (base + nn);
        sqT[d * 68 + nn] = g_q[((size_t)b * 256 + h * 64 + d) * NPIX + p];
        skv[d * 68 + nn] = g_kvdw[((size_t)b * 512 + h * 64 + d) * NPIX + p];
    }
    {
        const float* Sg = g_S + ((size_t)(bh * NCHUNK + ch)) * 4096;
        for (int i = tid; i < 4096; i += 256) sS[(i >> 6) * 68 + (i & 63)] = Sg[i];
    }
    if (tid < 64) sks[tid] = g_ksum[(bh * NCHUNK + ch) * 64 + tid];
    __syncthreads();

    {
        int n0 = (tid & 15) * 4, m0 = (tid >> 4) * 4;
        float a[4][4];
#pragma unroll
        for (int i = 0; i < 4; i++)
#pragma unroll
            for (int j = 0; j < 4; j++) a[i][j] = 0.f;
        for (int d = 0; d < 64; d++) {
            float4 q4 = *(const float4*)&sqT[d * 68 + n0];
            float4 k4 = *(const float4*)&skv[d * 68 + m0];
            float kv[4] = {k4.x, k4.y, k4.z, k4.w};
            float qv[4] = {q4.x, q4.y, q4.z, q4.w};
#pragma unroll
            for (int i = 0; i < 4; i++)
#pragma unroll
                for (int j = 0; j < 4; j++) a[i][j] += kv[i] * qv[j];
        }
        __syncthreads();
#pragma unroll
        for (int i = 0; i < 4; i++)
#pragma unroll
            for (int j = 0; j < 4; j++)
                sAT[(m0 + i) * 68 + (n0 + j)] = (m0 + i <= n0 + j) ? a[i][j] : 0.f;
    }
    for (int i = tid; i < 4096; i += 256) {
        int e = i >> 6, mm = i & 63;
        int p = rev ? (NPIX - 1 - (base + mm)) : (base + mm);
        skv[mm * 68 + e] = g_kvdw[((size_t)b * 512 + 256 + h * 64 + e) * NPIX + p];
    }
    __syncthreads();
    {
        int n = tid & 63, g = tid >> 6;
        float part = 0.f;
#pragma unroll
        for (int t = 0; t < 16; t++) {
            int m = g * 16 + t;
            part += sAT[m * 68 + n] + sqT[m * 68 + n] * sks[m];
        }
        sred[g * 64 + n] = part;
    }
    __syncthreads();

    int n0 = (tid & 15) * 4, e0 = (tid >> 4) * 4;
    float acc[4][4];
#pragma unroll
    for (int i = 0; i < 4; i++)
#pragma unroll
        for (int j = 0; j < 4; j++) acc[i][j] = 0.f;
    for (int m = 0; m < 64; m++) {
        float4 a4 = *(const float4*)&sAT[m * 68 + n0];
        float4 v4 = *(const float4*)&skv[m * 68 + e0];
        float vv[4] = {v4.x, v4.y, v4.z, v4.w};
        float av[4] = {a4.x, a4.y, a4.z, a4.w};
#pragma unroll
        for (int i = 0; i < 4; i++)
#pragma unroll
            for (int j = 0; j < 4; j++) acc[i][j] += vv[i] * av[j];
    }
    for (int d = 0; d < 64; d++) {
        float4 q4 = *(const float4*)&sqT[d * 68 + n0];
        float4 s4 = *(const float4*)&sS[d * 68 + e0];
        float sv4[4] = {s4.x, s4.y, s4.z, s4.w};
        float qv[4] = {q4.x, q4.y, q4.z, q4.w};
#pragma unroll
        for (int i = 0; i < 4; i++)
#pragma unroll
            for (int j = 0; j < 4; j++) acc[i][j] += sv4[i] * qv[j];
    }
    __syncthreads();
#pragma unroll
    for (int i = 0; i < 4; i++)
#pragma unroll
        for (int j = 0; j < 4; j++) sAT[(e0 + i) * 68 + (n0 + j)] = acc[i][j];
    if (tid < 64)
        srden[tid] = 1.f / (1e-6f + sred[tid] + sred[64 + tid] + sred[128 + tid] + sred[192 + tid]);
    __syncthreads();

    for (int i = tid; i < 4096; i += 256) {
        int e = i >> 6, nn = i & 63;
        int p = rev ? (NPIX - 1 - (base + nn)) : (base + nn);
        g_attn[((size_t)b * 256 + h * 64 + e) * NPIX + p] = sAT[e * 68 + nn] * srden[nn];
    }
}

// ---------------- launch ----------------
#define SMEM_TC4 ((2 * 64 * 36 + 2 * 32 * 132) * 4)
#define SMEM_TC2 ((2 * 64 * 36 + 2 * 32 * 68) * 4)

extern "C" void kernel_launch(void* const* d_in, const int* in_sizes, int n_in,
                              void* d_out, int out_size)
{
    (void)in_sizes; (void)n_in; (void)out_size;
    const float* x   = (const float*)d_in[0];
    const float* Wq  = (const float*)d_in[1];
    const float* bq  = (const float*)d_in[2];
    const float* Wa1 = (const float*)d_in[3];
    const float* Wdw = (const float*)d_in[4];
    const float* Wo  = (const float*)d_in[5];
    const float* bo  = (const float*)d_in[6];
    const float* Wg1 = (const float*)d_in[7];
    const float* bg1 = (const float*)d_in[8];
    const float* Wg2 = (const float*)d_in[9];
    const float* bg2 = (const float*)d_in[10];
    const float* Wg3 = (const float*)d_in[11];
    const float* bg3 = (const float*)d_in[12];
    float* out = (float*)d_out;

    float *qb, *kvb, *attnb, *g1b, *g2b, *gatedb, *whi, *wlo;
    cudaGetSymbolAddress((void**)&qb,    g_q);
    cudaGetSymbolAddress((void**)&kvb,   g_kv);
    cudaGetSymbolAddress((void**)&attnb, g_attn);
    cudaGetSymbolAddress((void**)&g1b,   g_g1);
    cudaGetSymbolAddress((void**)&g2b,   g_g2);
    cudaGetSymbolAddress((void**)&gatedb,g_gated);
    cudaGetSymbolAddress((void**)&whi,   g_Whi);
    cudaGetSymbolAddress((void**)&wlo,   g_Wlo);

    cudaFuncSetAttribute(gemm_tc<0, false, 4>, cudaFuncAttributeMaxDynamicSharedMemorySize, SMEM_TC4);
    cudaFuncSetAttribute(gemm_tc<2, false, 4>, cudaFuncAttributeMaxDynamicSharedMemorySize, SMEM_TC4);
    cudaFuncSetAttribute(gemm_tc<1, false, 2>, cudaFuncAttributeMaxDynamicSharedMemorySize, SMEM_TC2);
    cudaFuncSetAttribute(gemm_tc<1, true,  2>, cudaFuncAttributeMaxDynamicSharedMemorySize, SMEM_TC2);
    cudaFuncSetAttribute(attn_chunk_sums_tc, cudaFuncAttributeMaxDynamicSharedMemorySize, P1_SMEM_FLOATS * 4);
    cudaFuncSetAttribute(attn_out_k, cudaFuncAttributeMaxDynamicSharedMemorySize, P3_SMEM_FLOATS * 4);

    dim3 blk(256);
    cudaStream_t s0 = 0, s1 = g_si.s1;

    // weights split
    prep_split_k<<<dim3(512, 6), blk, 0, s0>>>(Wq, Wa1, Wg1, Wg2, Wg3, Wo);
    cudaEventRecord(g_si.evFork, s0);

    // ---- side stream: q GEMM, then gate chain g1 -> g2 ----
    cudaStreamWaitEvent(s1, g_si.evFork, 0);
    gemm_tc<2, false, 4><<<dim3(32, 4, 2), blk, SMEM_TC4, s1>>>(whi + OFF_Q, wlo + OFF_Q, x, bq, nullptr, qb, 256, 256);
    cudaEventRecord(g_si.evQ, s1);
    gemm_tc<1, false, 2><<<dim3(64, 1, 2), blk, SMEM_TC2, s1>>>(whi + OFF_G1, wlo + OFF_G1, x, bg1, nullptr, g1b, 64, 256);
    gemm_tc<1, true,  2><<<dim3(64, 1, 2), blk, SMEM_TC2, s1>>>(whi + OFF_G2, wlo + OFF_G2, g1b, bg2, nullptr, g2b, 64, 576);
    cudaEventRecord(g_si.evGate, s1);

    // ---- main stream: kv -> dwconv -> attention ----
    gemm_tc<0, false, 4><<<dim3(32, 8, 2), blk, SMEM_TC4, s0>>>(whi + OFF_A1, wlo + OFF_A1, x, nullptr, nullptr, kvb, 512, 256);
    dwconv_k<<<BATCH * 512, blk, 0, s0>>>(Wdw);
    attn_chunk_sums_tc<<<dim3(NCHUNK, NHEAD, BATCH), blk, P1_SMEM_FLOATS * 4, s0>>>();
    attn_prefix_k<<<dim3(16, BATCH * NHEAD), blk, 0, s0>>>();
    cudaStreamWaitEvent(s0, g_si.evQ, 0);          // attn_out needs q
    attn_out_k<<<dim3(NCHUNK, NHEAD, BATCH), blk, P3_SMEM_FLOATS * 4, s0>>>();

    // ---- tail: gated = (Wg3@g2 + bg3) * attn ; out = Wo@gated + bo ----
    cudaStreamWaitEvent(s0, g_si.evGate, 0);
    gemm_tc<0, false, 4><<<dim3(32, 4, 2), blk, SMEM_TC4, s0>>>(whi + OFF_G3, wlo + OFF_G3, g2b, bg3, attnb, gatedb, 256, 64);
    gemm_tc<0, false, 4><<<dim3(32, 4, 2), blk, SMEM_TC4, s0>>>(whi + OFF_O, wlo + OFF_O, gatedb, bo, nullptr, out, 256, 256);
}

// round 15
// speedup vs baseline: 1.1391x; 1.0300x over previous
#include <cuda_runtime.h>
#include <cstdint>
#include <cstddef>

#define BATCH 2
#define CCH   256
#define NPIX  4096
#define NHEAD 4
#define DDIM  64
#define NCHUNK 64

// ---------------- scratch ----------------
__device__ float g_q    [BATCH * CCH     * NPIX];
__device__ float g_kv   [BATCH * 2*CCH   * NPIX];
__device__ float g_kvdw [BATCH * 2*CCH   * NPIX];
__device__ float g_attn [BATCH * CCH     * NPIX];
__device__ float g_g1   [BATCH * 64      * NPIX];
__device__ float g_g2   [BATCH * 64      * NPIX];
__device__ float g_gated[BATCH * CCH     * NPIX];
__device__ float g_S    [BATCH * NHEAD * NCHUNK * DDIM * DDIM];
__device__ float g_ksum [BATCH * NHEAD * NCHUNK * DDIM];

// pre-split weights (hi/lo tf32, separate arrays)
#define OFF_Q  0
#define OFF_A1 65536
#define OFF_G1 196608
#define OFF_G2 212992
#define OFF_G3 249856
#define OFF_O  266240
#define W_TOTAL 331776
__device__ float g_Whi[W_TOTAL];
__device__ float g_Wlo[W_TOTAL];

// ---------------- streams/events (created at load, outside kernel_launch) ----------
struct StreamInit {
    cudaStream_t s1;
    cudaEvent_t evFork, evGate;
    StreamInit() {
        cudaStreamCreateWithFlags(&s1, cudaStreamNonBlocking);
        cudaEventCreateWithFlags(&evFork, cudaEventDisableTiming);
        cudaEventCreateWithFlags(&evGate, cudaEventDisableTiming);
    }
};
static StreamInit g_si;

__device__ __forceinline__ float elup1(float x) { return x > 0.f ? x + 1.f : __expf(x); }

__device__ __forceinline__ void tf32split(float v, float& hi, float& lo) {
    uint32_t u;
    asm("cvt.rna.tf32.f32 %0, %1;" : "=r"(u) : "f"(v));
    hi = __uint_as_float(u);
    float r = v - hi;
    uint32_t u2;
    asm("cvt.rna.tf32.f32 %0, %1;" : "=r"(u2) : "f"(r));
    lo = __uint_as_float(u2);
}

__device__ __forceinline__ void mma8(float* c, const uint32_t* a, const uint32_t* b) {
    asm volatile(
        "mma.sync.aligned.m16n8k8.row.col.f32.tf32.tf32.f32 "
        "{%0,%1,%2,%3},{%4,%5,%6,%7},{%8,%9},{%0,%1,%2,%3};"
        : "+f"(c[0]), "+f"(c[1]), "+f"(c[2]), "+f"(c[3])
        : "r"(a[0]), "r"(a[1]), "r"(a[2]), "r"(a[3]), "r"(b[0]), "r"(b[1]));
}

// ---------------- weight split prep ----------------
__global__ __launch_bounds__(256) void prep_split_k(
    const float* __restrict__ Wq, const float* __restrict__ Wa1,
    const float* __restrict__ Wg1, const float* __restrict__ Wg2,
    const float* __restrict__ Wg3, const float* __restrict__ Wo)
{
    const float* src; int off, len;
    switch (blockIdx.y) {
        case 0:  src = Wq;  off = OFF_Q;  len = 65536;  break;
        case 1:  src = Wa1; off = OFF_A1; len = 131072; break;
        case 2:  src = Wg1; off = OFF_G1; len = 16384;  break;
        case 3:  src = Wg2; off = OFF_G2; len = 36864;  break;
        case 4:  src = Wg3; off = OFF_G3; len = 16384;  break;
        default: src = Wo;  off = OFF_O;  len = 65536;  break;
    }
    for (int i = blockIdx.x * 256 + threadIdx.x; i < len; i += gridDim.x * 256) {
        float h, l;
        tf32split(src[i], h, l);
        g_Whi[off + i] = h;
        g_Wlo[off + i] = l;
    }
}

// ---------------- tensor-core GEMM core (round-6/10 proven version) ----------------
template<int ACT, bool CONV, int NF>
__device__ __forceinline__ void gemm_core(
    const float* __restrict__ Ahi, const float* __restrict__ Alo,
    const float* __restrict__ X,
    const float* __restrict__ bias, const float* __restrict__ mul,
    float* __restrict__ Y, int O, int K, int oby)
{
    constexpr int COLS = NF * 32;
    constexpr int BST  = COLS + 4;
    extern __shared__ __align__(16) float sm[];
    float* Ah = sm;                        // 64 x 36
    float* Al = Ah + 64 * 36;
    float* Bh = Al + 64 * 36;              // 32 x BST
    float* Bl = Bh + 32 * BST;

    const int tid = threadIdx.x;
    const int lane = tid & 31, warp = tid >> 5;
    const int wn = warp & 3, wm = warp >> 2;
    const int obase = oby * 64, nbase = blockIdx.x * COLS, b = blockIdx.z;
    const int Cin = CONV ? (K / 9) : K;
    const float* Xb = X + (size_t)b * (size_t)Cin * NPIX;

    float acc[2][NF][4];
#pragma unroll
    for (int i = 0; i < 2; i++)
#pragma unroll
        for (int j = 0; j < NF; j++)
#pragma unroll
            for (int r = 0; r < 4; r++) acc[i][j][r] = 0.f;

    float4 pb[NF];
    if (!CONV) {
#pragma unroll
        for (int t = 0; t < NF; t++) {
            int i = tid + t * 256;
            int kk = i / (NF * 8), nq = i % (NF * 8);
            pb[t] = *(const float4*)&Xb[(size_t)kk * NPIX + nbase + nq * 4];
        }
    }

    for (int k0 = 0; k0 < K; k0 += 32) {
        // ---- stage A (pre-split copy) ----
#pragma unroll
        for (int t = 0; t < 2; t++) {
            int ii = tid + t * 256;
            int oo = ii >> 3, kq2 = ii & 7;
            size_t gi = (size_t)(obase + oo) * K + k0 + kq2 * 4;
            *(float4*)&Ah[oo * 36 + kq2 * 4] = *(const float4*)&Ahi[gi];
            *(float4*)&Al[oo * 36 + kq2 * 4] = *(const float4*)&Alo[gi];
        }
        // ---- stage B ----
        if (!CONV) {
#pragma unroll
            for (int t = 0; t < NF; t++) {
                int i = tid + t * 256;
                int kk = i / (NF * 8), nq = i % (NF * 8);
                float4 b4 = pb[t];
                float4 h4, l4;
                tf32split(b4.x, h4.x, l4.x); tf32split(b4.y, h4.y, l4.y);
                tf32split(b4.z, h4.z, l4.z); tf32split(b4.w, h4.w, l4.w);
                *(float4*)&Bh[kk * BST + nq * 4] = h4;
                *(float4*)&Bl[kk * BST + nq * 4] = l4;
            }
        } else {
#pragma unroll
            for (int t = 0; t < NF * 4; t++) {
                int i = tid + t * 256;
                int kk = i / COLS, nn = i % COLS;
                int k = k0 + kk;
                int ic = k / 9, tp = k - ic * 9;
                int dy = tp / 3 - 1, dx = tp - (tp / 3) * 3 - 1;
                int n = nbase + nn;
                int y = n >> 6, x = n & 63;
                int yy = y + dy, xx = x + dx;
                float v = 0.f;
                if (yy >= 0 && yy < 64 && xx >= 0 && xx < 64)
                    v = Xb[(size_t)ic * NPIX + yy * 64 + xx];
                float h, l;
                tf32split(v, h, l);
                Bh[kk * BST + nn] = h;
                Bl[kk * BST + nn] = l;
            }
        }
        __syncthreads();

        if (!CONV && k0 + 32 < K) {
#pragma unroll
            for (int t = 0; t < NF; t++) {
                int i = tid + t * 256;
                int kk = i / (NF * 8), nq = i % (NF * 8);
                pb[t] = *(const float4*)&Xb[(size_t)(k0 + 32 + kk) * NPIX + nbase + nq * 4];
            }
        }

#pragma unroll
        for (int ks = 0; ks < 4; ks++) {
            const int kb = ks * 8 + (lane & 3);
            uint32_t bh[NF][2], bl[NF][2];
#pragma unroll
            for (int nf = 0; nf < NF; nf++) {
                int col = wn * (NF * 8) + nf * 8 + (lane >> 2);
                bh[nf][0] = __float_as_uint(Bh[kb * BST + col]);
                bh[nf][1] = __float_as_uint(Bh[(kb + 4) * BST + col]);
                bl[nf][0] = __float_as_uint(Bl[kb * BST + col]);
                bl[nf][1] = __float_as_uint(Bl[(kb + 4) * BST + col]);
            }
#pragma unroll
            for (int mf = 0; mf < 2; mf++) {
                int row = wm * 32 + mf * 16 + (lane >> 2);
                uint32_t ah[4], al[4];
                ah[0] = __float_as_uint(Ah[row * 36 + kb]);
                ah[1] = __float_as_uint(Ah[(row + 8) * 36 + kb]);
                ah[2] = __float_as_uint(Ah[row * 36 + kb + 4]);
                ah[3] = __float_as_uint(Ah[(row + 8) * 36 + kb + 4]);
                al[0] = __float_as_uint(Al[row * 36 + kb]);
                al[1] = __float_as_uint(Al[(row + 8) * 36 + kb]);
                al[2] = __float_as_uint(Al[row * 36 + kb + 4]);
                al[3] = __float_as_uint(Al[(row + 8) * 36 + kb + 4]);
#pragma unroll
                for (int nf = 0; nf < NF; nf++) {
                    mma8(acc[mf][nf], ah, bh[nf]);
                    mma8(acc[mf][nf], ah, bl[nf]);
                    mma8(acc[mf][nf], al, bh[nf]);
                }
            }
        }
        __syncthreads();
    }

    // ---- epilogue ----
#pragma unroll
    for (int mf = 0; mf < 2; mf++) {
        int o0 = obase + wm * 32 + mf * 16 + (lane >> 2);
        int o1 = o0 + 8;
        float bi0 = bias ? bias[o0] : 0.f;
        float bi1 = bias ? bias[o1] : 0.f;
        size_t r0 = ((size_t)b * O + o0) * NPIX;
        size_t r1 = ((size_t)b * O + o1) * NPIX;
#pragma unroll
        for (int nf = 0; nf < NF; nf++) {
            int n = nbase + wn * (NF * 8) + nf * 8 + 2 * (lane & 3);
            float v00 = acc[mf][nf][0] + bi0, v01 = acc[mf][nf][1] + bi0;
            float v10 = acc[mf][nf][2] + bi1, v11 = acc[mf][nf][3] + bi1;
            if (ACT == 1) {
                v00 = v00 > 0.f ? v00 : 0.2f * v00; v01 = v01 > 0.f ? v01 : 0.2f * v01;
                v10 = v10 > 0.f ? v10 : 0.2f * v10; v11 = v11 > 0.f ? v11 : 0.2f * v11;
            }
            if (ACT == 2) { v00 = elup1(v00); v01 = elup1(v01); v10 = elup1(v10); v11 = elup1(v11); }
            if (mul) {
                v00 *= mul[r0 + n]; v01 *= mul[r0 + n + 1];
                v10 *= mul[r1 + n]; v11 *= mul[r1 + n + 1];
            }
            *(float2*)&Y[r0 + n] = make_float2(v00, v01);
            *(float2*)&Y[r1 + n] = make_float2(v10, v11);
        }
    }
}

template<int ACT, bool CONV, int NF>
__global__ __launch_bounds__(256, 2) void gemm_tc(
    const float* __restrict__ Ahi, const float* __restrict__ Alo,
    const float* __restrict__ X,
    const float* __restrict__ bias, const float* __restrict__ mul,
    float* __restrict__ Y, int O, int K)
{
    gemm_core<ACT, CONV, NF>(Ahi, Alo, X, bias, mul, Y, O, K, blockIdx.y);
}

// fused q + kv GEMM: y 0-3 -> q (elup1, bias), y 4-11 -> kv (round-6 config)
__global__ __launch_bounds__(256, 2) void gemm_qkv_k(
    const float* __restrict__ x, const float* __restrict__ bq,
    float* __restrict__ qout, float* __restrict__ kvout)
{
    if (blockIdx.y < 4)
        gemm_core<2, false, 4>(g_Whi + OFF_Q, g_Wlo + OFF_Q, x, bq, nullptr, qout, 256, 256, blockIdx.y);
    else
        gemm_core<0, false, 4>(g_Whi + OFF_A1, g_Wlo + OFF_A1, x, nullptr, nullptr, kvout, 512, 256, blockIdx.y - 4);
}

// ---------------- depthwise 3x3 SAME ----------------
__global__ __launch_bounds__(256) void dwconv_k(const float* __restrict__ W)
{
    __shared__ float sp[66][68];
    int c = blockIdx.x & 511, b = blockIdx.x >> 9;
    const float* Xc = g_kv + ((size_t)(b * 512 + c)) * NPIX;
    float* Oc = g_kvdw + ((size_t)(b * 512 + c)) * NPIX;

    for (int i = threadIdx.x; i < 66 * 66; i += 256) {
        int r = i / 66, col = i - r * 66;
        int y = r - 1, x = col - 1;
        sp[r][col] = (y >= 0 && y < 64 && x >= 0 && x < 64) ? Xc[y * 64 + x] : 0.f;
    }
    float w[9];
#pragma unroll
    for (int j = 0; j < 9; j++) w[j] = W[c * 9 + j];
    __syncthreads();

    bool isk = (c < 256);
    for (int i = threadIdx.x; i < 4096; i += 256) {
        int y = i >> 6, x = i & 63;
        float acc = 0.f;
#pragma unroll
        for (int dy = 0; dy < 3; dy++)
#pragma unroll
            for (int dx = 0; dx < 3; dx++)
                acc += w[dy * 3 + dx] * sp[y + dy][x + dx];
        Oc[i] = isk ? elup1(acc) : acc;
    }
}

// ---------------- attention phase 1 (TENSOR CORE): S_c = k^T v, ksum_c -------------
#define P1_SMEM_FLOATS (4 * 64 * 68 + 256)
__global__ __launch_bounds__(256, 2) void attn_chunk_sums_tc()
{
    extern __shared__ __align__(16) float sm[];
    float* Ah = sm;                 // [d][n] stride 68
    float* Al = Ah + 64 * 68;
    float* Bh = Al + 64 * 68;       // [n][e] stride 68
    float* Bl = Bh + 64 * 68;
    float* sred = Bl + 64 * 68;     // 256

    const int tid = threadIdx.x;
    const int lane = tid & 31, warp = tid >> 5;
    const int wn = warp & 3, wm = warp >> 2;
    int ch = blockIdx.x, h = blockIdx.y, b = blockIdx.z;
    bool rev = (h >= 2);
    int base = ch * 64;
    int bh_idx = b * NHEAD + h;

    for (int i = tid; i < 4096; i += 256) {
        int d = i >> 6, nn = i & 63;
        int p = rev ? (NPIX - 1 - (base + nn)) : (base + nn);
        size_t off = ((size_t)b * 512 + h * 64 + d) * NPIX + p;
        float kvk = g_kvdw[off];
        float kvv = g_kvdw[off + (size_t)256 * NPIX];
        float hh, ll;
        tf32split(kvk, hh, ll);
        Ah[d * 68 + nn] = hh; Al[d * 68 + nn] = ll;
        tf32split(kvv, hh, ll);
        Bh[nn * 68 + d] = hh; Bl[nn * 68 + d] = ll;
    }
    __syncthreads();

    float acc[2][2][4];
#pragma unroll
    for (int i = 0; i < 2; i++)
#pragma unroll
        for (int j = 0; j < 2; j++)
#pragma unroll
            for (int r = 0; r < 4; r++) acc[i][j][r] = 0.f;

#pragma unroll
    for (int ks = 0; ks < 8; ks++) {
        const int kb = ks * 8 + (lane & 3);
        uint32_t bh2[2][2], bl2[2][2];
#pragma unroll
        for (int nf = 0; nf < 2; nf++) {
            int col = wn * 16 + nf * 8 + (lane >> 2);
            bh2[nf][0] = __float_as_uint(Bh[kb * 68 + col]);
            bh2[nf][1] = __float_as_uint(Bh[(kb + 4) * 68 + col]);
            bl2[nf][0] = __float_as_uint(Bl[kb * 68 + col]);
            bl2[nf][1] = __float_as_uint(Bl[(kb + 4) * 68 + col]);
        }
#pragma unroll
        for (int mf = 0; mf < 2; mf++) {
            int row = wm * 32 + mf * 16 + (lane >> 2);
            uint32_t ah[4], al[4];
            ah[0] = __float_as_uint(Ah[row * 68 + kb]);
            ah[1] = __float_as_uint(Ah[(row + 8) * 68 + kb]);
            ah[2] = __float_as_uint(Ah[row * 68 + kb + 4]);
            ah[3] = __float_as_uint(Ah[(row + 8) * 68 + kb + 4]);
            al[0] = __float_as_uint(Al[row * 68 + kb]);
            al[1] = __float_as_uint(Al[(row + 8) * 68 + kb]);
            al[2] = __float_as_uint(Al[row * 68 + kb + 4]);
            al[3] = __float_as_uint(Al[(row + 8) * 68 + kb + 4]);
#pragma unroll
            for (int nf = 0; nf < 2; nf++) {
                mma8(acc[mf][nf], ah, bh2[nf]);
                mma8(acc[mf][nf], ah, bl2[nf]);
                mma8(acc[mf][nf], al, bh2[nf]);
            }
        }
    }

    float* Sg = g_S + ((size_t)(bh_idx * NCHUNK + ch)) * 4096;
#pragma unroll
    for (int mf = 0; mf < 2; mf++) {
        int d0 = wm * 32 + mf * 16 + (lane >> 2);
        int d1 = d0 + 8;
#pragma unroll
        for (int nf = 0; nf < 2; nf++) {
            int e = wn * 16 + nf * 8 + 2 * (lane & 3);
            *(float2*)&Sg[d0 * 64 + e] = make_float2(acc[mf][nf][0], acc[mf][nf][1]);
            *(float2*)&Sg[d1 * 64 + e] = make_float2(acc[mf][nf][2], acc[mf][nf][3]);
        }
    }

    {
        int d = tid & 63, g = tid >> 6;
        float part = 0.f;
#pragma unroll
        for (int t = 0; t < 16; t++) {
            int nn = g * 16 + t;
            part += Ah[d * 68 + nn] + Al[d * 68 + nn];
        }
        sred[g * 64 + d] = part;
    }
    __syncthreads();
    if (tid < 64)
        g_ksum[(bh_idx * NCHUNK + ch) * 64 + tid] =
            sred[tid] + sred[64 + tid] + sred[128 + tid] + sred[192 + tid];
}

// ---------------- attention phase 2 ----------------
__global__ __launch_bounds__(256) void attn_prefix_k()
{
    int bh = blockIdx.y;
    int e = blockIdx.x * 256 + threadIdx.x;
    float* Sg = g_S + (size_t)bh * NCHUNK * 4096;
    float run = 0.f;
#pragma unroll 4
    for (int c = 0; c < NCHUNK; c++) {
        float v = Sg[(size_t)c * 4096 + e];
        Sg[(size_t)c * 4096 + e] = run;
        run += v;
    }
    if (blockIdx.x == 0 && threadIdx.x < 64) {
        int d = threadIdx.x;
        float r2 = 0.f;
        for (int c = 0; c < NCHUNK; c++) {
            float v = g_ksum[(bh * NCHUNK + c) * 64 + d];
            g_ksum[(bh * NCHUNK + c) * 64 + d] = r2;
            r2 += v;
        }
    }
}

// ---------------- attention phase 3 ----------------
#define P3_SMEM_FLOATS (4 * 64 * 68 + 64 + 64 + 256)
__global__ __launch_bounds__(256) void attn_out_k()
{
    extern __shared__ __align__(16) float sm[];
    float* sqT = sm;
    float* skv = sm + 4352;
    float* sAT = sm + 8704;
    float* sS  = sm + 13056;
    float* sks   = sm + 17408;
    float* srden = sm + 17472;
    float* sred  = sm + 17536;

    int tid = threadIdx.x;
    int ch = blockIdx.x, h = blockIdx.y, b = blockIdx.z;
    bool rev = (h >= 2);
    int base = ch * 64;
    int bh = b * NHEAD + h;

    for (int i = tid; i < 4096; i += 256) {
        int d = i >> 6, nn = i & 63;
        int p = rev ? (NPIX - 1 - (base + nn)) : (base + nn);
        sqT[d * 68 + nn] = g_q[((size_t)b * 256 + h * 64 + d) * NPIX + p];
        skv[d * 68 + nn] = g_kvdw[((size_t)b * 512 + h * 64 + d) * NPIX + p];
    }
    {
        const float* Sg = g_S + ((size_t)(bh * NCHUNK + ch)) * 4096;
        for (int i = tid; i < 4096; i += 256) sS[(i >> 6) * 68 + (i & 63)] = Sg[i];
    }
    if (tid < 64) sks[tid] = g_ksum[(bh * NCHUNK + ch) * 64 + tid];
    __syncthreads();

    {
        int n0 = (tid & 15) * 4, m0 = (tid >> 4) * 4;
        float a[4][4];
#pragma unroll
        for (int i = 0; i < 4; i++)
#pragma unroll
            for (int j = 0; j < 4; j++) a[i][j] = 0.f;
        for (int d = 0; d < 64; d++) {
            float4 q4 = *(const float4*)&sqT[d * 68 + n0];
            float4 k4 = *(const float4*)&skv[d * 68 + m0];
            float kv[4] = {k4.x, k4.y, k4.z, k4.w};
            float qv[4] = {q4.x, q4.y, q4.z, q4.w};
#pragma unroll
            for (int i = 0; i < 4; i++)
#pragma unroll
                for (int j = 0; j < 4; j++) a[i][j] += kv[i] * qv[j];
        }
        __syncthreads();
#pragma unroll
        for (int i = 0; i < 4; i++)
#pragma unroll
            for (int j = 0; j < 4; j++)
                sAT[(m0 + i) * 68 + (n0 + j)] = (m0 + i <= n0 + j) ? a[i][j] : 0.f;
    }
    for (int i = tid; i < 4096; i += 256) {
        int e = i >> 6, mm = i & 63;
        int p = rev ? (NPIX - 1 - (base + mm)) : (base + mm);
        skv[mm * 68 + e] = g_kvdw[((size_t)b * 512 + 256 + h * 64 + e) * NPIX + p];
    }
    __syncthreads();
    {
        int n = tid & 63, g = tid >> 6;
        float part = 0.f;
#pragma unroll
        for (int t = 0; t < 16; t++) {
            int m = g * 16 + t;
            part += sAT[m * 68 + n] + sqT[m * 68 + n] * sks[m];
        }
        sred[g * 64 + n] = part;
    }
    __syncthreads();

    int n0 = (tid & 15) * 4, e0 = (tid >> 4) * 4;
    float acc[4][4];
#pragma unroll
    for (int i = 0; i < 4; i++)
#pragma unroll
        for (int j = 0; j < 4; j++) acc[i][j] = 0.f;
    for (int m = 0; m < 64; m++) {
        float4 a4 = *(const float4*)&sAT[m * 68 + n0];
        float4 v4 = *(const float4*)&skv[m * 68 + e0];
        float vv[4] = {v4.x, v4.y, v4.z, v4.w};
        float av[4] = {a4.x, a4.y, a4.z, a4.w};
#pragma unroll
        for (int i = 0; i < 4; i++)
#pragma unroll
            for (int j = 0; j < 4; j++) acc[i][j] += vv[i] * av[j];
    }
    for (int d = 0; d < 64; d++) {
        float4 q4 = *(const float4*)&sqT[d * 68 + n0];
        float4 s4 = *(const float4*)&sS[d * 68 + e0];
        float sv4[4] = {s4.x, s4.y, s4.z, s4.w};
        float qv[4] = {q4.x, q4.y, q4.z, q4.w};
#pragma unroll
        for (int i = 0; i < 4; i++)
#pragma unroll
            for (int j = 0; j < 4; j++) acc[i][j] += sv4[i] * qv[j];
    }
    __syncthreads();
#pragma unroll
    for (int i = 0; i < 4; i++)
#pragma unroll
        for (int j = 0; j < 4; j++) sAT[(e0 + i) * 68 + (n0 + j)] = acc[i][j];
    if (tid < 64)
        srden[tid] = 1.f / (1e-6f + sred[tid] + sred[64 + tid] + sred[128 + tid] + sred[192 + tid]);
    __syncthreads();

    for (int i = tid; i < 4096; i += 256) {
        int e = i >> 6, nn = i & 63;
        int p = rev ? (NPIX - 1 - (base + nn)) : (base + nn);
        g_attn[((size_t)b * 256 + h * 64 + e) * NPIX + p] = sAT[e * 68 + nn] * srden[nn];
    }
}

// ---------------- launch ----------------
#define SMEM_TC4 ((2 * 64 * 36 + 2 * 32 * 132) * 4)

extern "C" void kernel_launch(void* const* d_in, const int* in_sizes, int n_in,
                              void* d_out, int out_size)
{
    (void)in_sizes; (void)n_in; (void)out_size;
    const float* x   = (const float*)d_in[0];
    const float* Wq  = (const float*)d_in[1];
    const float* bq  = (const float*)d_in[2];
    const float* Wa1 = (const float*)d_in[3];
    const float* Wdw = (const float*)d_in[4];
    const float* Wo  = (const float*)d_in[5];
    const float* bo  = (const float*)d_in[6];
    const float* Wg1 = (const float*)d_in[7];
    const float* bg1 = (const float*)d_in[8];
    const float* Wg2 = (const float*)d_in[9];
    const float* bg2 = (const float*)d_in[10];
    const float* Wg3 = (const float*)d_in[11];
    const float* bg3 = (const float*)d_in[12];
    float* out = (float*)d_out;

    float *qb, *kvb, *attnb, *g1b, *g2b, *gatedb, *whi, *wlo;
    cudaGetSymbolAddress((void**)&qb,    g_q);
    cudaGetSymbolAddress((void**)&kvb,   g_kv);
    cudaGetSymbolAddress((void**)&attnb, g_attn);
    cudaGetSymbolAddress((void**)&g1b,   g_g1);
    cudaGetSymbolAddress((void**)&g2b,   g_g2);
    cudaGetSymbolAddress((void**)&gatedb,g_gated);
    cudaGetSymbolAddress((void**)&whi,   g_Whi);
    cudaGetSymbolAddress((void**)&wlo,   g_Wlo);

    cudaFuncSetAttribute(gemm_qkv_k, cudaFuncAttributeMaxDynamicSharedMemorySize, SMEM_TC4);
    cudaFuncSetAttribute(gemm_tc<0, false, 4>, cudaFuncAttributeMaxDynamicSharedMemorySize, SMEM_TC4);
    cudaFuncSetAttribute(gemm_tc<1, false, 4>, cudaFuncAttributeMaxDynamicSharedMemorySize, SMEM_TC4);
    cudaFuncSetAttribute(gemm_tc<1, true,  4>, cudaFuncAttributeMaxDynamicSharedMemorySize, SMEM_TC4);
    cudaFuncSetAttribute(attn_chunk_sums_tc, cudaFuncAttributeMaxDynamicSharedMemorySize, P1_SMEM_FLOATS * 4);
    cudaFuncSetAttribute(attn_out_k, cudaFuncAttributeMaxDynamicSharedMemorySize, P3_SMEM_FLOATS * 4);

    dim3 blk(256);
    cudaStream_t s0 = 0, s1 = g_si.s1;

    // weights split (both branches need it)
    prep_split_k<<<dim3(512, 6), blk, 0, s0>>>(Wq, Wa1, Wg1, Wg2, Wg3, Wo);
    cudaEventRecord(g_si.evFork, s0);

    // ---- side branch: gate conv chain (round-6 config: 128-wide tiles) ----
    cudaStreamWaitEvent(s1, g_si.evFork, 0);
    gemm_tc<1, false, 4><<<dim3(32, 1, 2), blk, SMEM_TC4, s1>>>(whi + OFF_G1, wlo + OFF_G1, x, bg1, nullptr, g1b, 64, 256);
    gemm_tc<1, true,  4><<<dim3(32, 1, 2), blk, SMEM_TC4, s1>>>(whi + OFF_G2, wlo + OFF_G2, g1b, bg2, nullptr, g2b, 64, 576);
    cudaEventRecord(g_si.evGate, s1);

    // ---- main branch: q/kv (fused) -> dwconv -> attention ----
    gemm_qkv_k<<<dim3(32, 12, 2), blk, SMEM_TC4, s0>>>(x, bq, qb, kvb);
    dwconv_k<<<BATCH * 512, blk, 0, s0>>>(Wdw);
    attn_chunk_sums_tc<<<dim3(NCHUNK, NHEAD, BATCH), blk, P1_SMEM_FLOATS * 4, s0>>>();
    attn_prefix_k<<<dim3(16, BATCH * NHEAD), blk, 0, s0>>>();
    attn_out_k<<<dim3(NCHUNK, NHEAD, BATCH), blk, P3_SMEM_FLOATS * 4, s0>>>();

    // ---- join: g3 needs both attn (s0) and g2 (s1) ----
    cudaStreamWaitEvent(s0, g_si.evGate, 0);
    gemm_tc<0, false, 4><<<dim3(32, 4, 2), blk, SMEM_TC4, s0>>>(whi + OFF_G3, wlo + OFF_G3, g2b, bg3, attnb, gatedb, 256, 64);
    gemm_tc<0, false, 4><<<dim3(32, 4, 2), blk, SMEM_TC4, s0>>>(whi + OFF_O, wlo + OFF_O, gatedb, bo, nullptr, out, 256, 256);
}

// round 16
// speedup vs baseline: 1.1598x; 1.0182x over previous
#include <cuda_runtime.h>
#include <cstdint>
#include <cstddef>

#define BATCH 2
#define CCH   256
#define NPIX  4096
#define NHEAD 4
#define DDIM  64
#define NCHUNK 64

// ---------------- scratch ----------------
__device__ float g_q    [BATCH * CCH     * NPIX];
__device__ float g_kv   [BATCH * 2*CCH   * NPIX];
__device__ float g_kvdw [BATCH * 2*CCH   * NPIX];
__device__ float g_attn [BATCH * CCH     * NPIX];
__device__ float g_g1   [BATCH * 64      * NPIX];
__device__ float g_g2   [BATCH * 64      * NPIX];
__device__ float g_gated[BATCH * CCH     * NPIX];
__device__ float g_S    [BATCH * NHEAD * NCHUNK * DDIM * DDIM];
__device__ float g_ksum [BATCH * NHEAD * NCHUNK * DDIM];

// pre-split weights (hi/lo tf32, separate arrays)
#define OFF_Q  0
#define OFF_A1 65536
#define OFF_G1 196608
#define OFF_G2 212992
#define OFF_G3 249856
#define OFF_O  266240
#define W_TOTAL 331776
__device__ float g_Whi[W_TOTAL];
__device__ float g_Wlo[W_TOTAL];

// ---------------- streams/events (created at load, outside kernel_launch) ----------
struct StreamInit {
    cudaStream_t s1;
    cudaEvent_t evFork, evGate;
    StreamInit() {
        cudaStreamCreateWithFlags(&s1, cudaStreamNonBlocking);
        cudaEventCreateWithFlags(&evFork, cudaEventDisableTiming);
        cudaEventCreateWithFlags(&evGate, cudaEventDisableTiming);
    }
};
static StreamInit g_si;

__device__ __forceinline__ float elup1(float x) { return x > 0.f ? x + 1.f : __expf(x); }

__device__ __forceinline__ void tf32split(float v, float& hi, float& lo) {
    uint32_t u;
    asm("cvt.rna.tf32.f32 %0, %1;" : "=r"(u) : "f"(v));
    hi = __uint_as_float(u);
    float r = v - hi;
    uint32_t u2;
    asm("cvt.rna.tf32.f32 %0, %1;" : "=r"(u2) : "f"(r));
    lo = __uint_as_float(u2);
}

__device__ __forceinline__ void mma8(float* c, const uint32_t* a, const uint32_t* b) {
    asm volatile(
        "mma.sync.aligned.m16n8k8.row.col.f32.tf32.tf32.f32 "
        "{%0,%1,%2,%3},{%4,%5,%6,%7},{%8,%9},{%0,%1,%2,%3};"
        : "+f"(c[0]), "+f"(c[1]), "+f"(c[2]), "+f"(c[3])
        : "r"(a[0]), "r"(a[1]), "r"(a[2]), "r"(a[3]), "r"(b[0]), "r"(b[1]));
}

// ldmatrix x4 on 32-bit data: thread i receives f32 (row i/4, col i%4) of each 8x4-f32 tile
__device__ __forceinline__ void ldsm4(uint32_t* r, uint32_t saddr) {
    asm volatile("ldmatrix.sync.aligned.m8n8.x4.shared.b16 {%0,%1,%2,%3}, [%4];"
                 : "=r"(r[0]), "=r"(r[1]), "=r"(r[2]), "=r"(r[3]) : "r"(saddr));
}

// ---------------- weight split prep ----------------
__global__ __launch_bounds__(256) void prep_split_k(
    const float* __restrict__ Wq, const float* __restrict__ Wa1,
    const float* __restrict__ Wg1, const float* __restrict__ Wg2,
    const float* __restrict__ Wg3, const float* __restrict__ Wo)
{
    const float* src; int off, len;
    switch (blockIdx.y) {
        case 0:  src = Wq;  off = OFF_Q;  len = 65536;  break;
        case 1:  src = Wa1; off = OFF_A1; len = 131072; break;
        case 2:  src = Wg1; off = OFF_G1; len = 16384;  break;
        case 3:  src = Wg2; off = OFF_G2; len = 36864;  break;
        case 4:  src = Wg3; off = OFF_G3; len = 16384;  break;
        default: src = Wo;  off = OFF_O;  len = 65536;  break;
    }
    for (int i = blockIdx.x * 256 + threadIdx.x; i < len; i += gridDim.x * 256) {
        float h, l;
        tf32split(src[i], h, l);
        g_Whi[off + i] = h;
        g_Wlo[off + i] = l;
    }
}

// ---------------- tensor-core GEMM core (A fragments via ldmatrix) ----------------
template<int ACT, bool CONV, int NF>
__device__ __forceinline__ void gemm_core(
    const float* __restrict__ Ahi, const float* __restrict__ Alo,
    const float* __restrict__ X,
    const float* __restrict__ bias, const float* __restrict__ mul,
    float* __restrict__ Y, int O, int K, int oby)
{
    constexpr int COLS = NF * 32;
    constexpr int BST  = COLS + 4;
    extern __shared__ __align__(16) float sm[];
    float* Ah = sm;                        // 64 x 36
    float* Al = Ah + 64 * 36;
    float* Bh = Al + 64 * 36;              // 32 x BST
    float* Bl = Bh + 32 * BST;

    const int tid = threadIdx.x;
    const int lane = tid & 31, warp = tid >> 5;
    const int wn = warp & 3, wm = warp >> 2;
    const int obase = oby * 64, nbase = blockIdx.x * COLS, b = blockIdx.z;
    const int Cin = CONV ? (K / 9) : K;
    const float* Xb = X + (size_t)b * (size_t)Cin * NPIX;

    // ldmatrix base addresses for A fragments: lane L -> row r+(L&15), col (L>>4)*4
    const uint32_t smem_base = (uint32_t)__cvta_generic_to_shared(sm);
    uint32_t aAh[2], aAl[2];
#pragma unroll
    for (int mf = 0; mf < 2; mf++) {
        int r = wm * 32 + mf * 16;
        uint32_t off = ((r + (lane & 15)) * 36 + (lane >> 4) * 4) * 4;
        aAh[mf] = smem_base + off;
        aAl[mf] = smem_base + 64 * 36 * 4 + off;
    }

    float acc[2][NF][4];
#pragma unroll
    for (int i = 0; i < 2; i++)
#pragma unroll
        for (int j = 0; j < NF; j++)
#pragma unroll
            for (int r = 0; r < 4; r++) acc[i][j][r] = 0.f;

    float4 pb[NF];
    if (!CONV) {
#pragma unroll
        for (int t = 0; t < NF; t++) {
            int i = tid + t * 256;
            int kk = i / (NF * 8), nq = i % (NF * 8);
            pb[t] = *(const float4*)&Xb[(size_t)kk * NPIX + nbase + nq * 4];
        }
    }

    for (int k0 = 0; k0 < K; k0 += 32) {
        // ---- stage A (pre-split copy) ----
#pragma unroll
        for (int t = 0; t < 2; t++) {
            int ii = tid + t * 256;
            int oo = ii >> 3, kq2 = ii & 7;
            size_t gi = (size_t)(obase + oo) * K + k0 + kq2 * 4;
            *(float4*)&Ah[oo * 36 + kq2 * 4] = *(const float4*)&Ahi[gi];
            *(float4*)&Al[oo * 36 + kq2 * 4] = *(const float4*)&Alo[gi];
        }
        // ---- stage B ----
        if (!CONV) {
#pragma unroll
            for (int t = 0; t < NF; t++) {
                int i = tid + t * 256;
                int kk = i / (NF * 8), nq = i % (NF * 8);
                float4 b4 = pb[t];
                float4 h4, l4;
                tf32split(b4.x, h4.x, l4.x); tf32split(b4.y, h4.y, l4.y);
                tf32split(b4.z, h4.z, l4.z); tf32split(b4.w, h4.w, l4.w);
                *(float4*)&Bh[kk * BST + nq * 4] = h4;
                *(float4*)&Bl[kk * BST + nq * 4] = l4;
            }
        } else {
#pragma unroll
            for (int t = 0; t < NF * 4; t++) {
                int i = tid + t * 256;
                int kk = i / COLS, nn = i % COLS;
                int k = k0 + kk;
                int ic = k / 9, tp = k - ic * 9;
                int dy = tp / 3 - 1, dx = tp - (tp / 3) * 3 - 1;
                int n = nbase + nn;
                int y = n >> 6, x = n & 63;
                int yy = y + dy, xx = x + dx;
                float v = 0.f;
                if (yy >= 0 && yy < 64 && xx >= 0 && xx < 64)
                    v = Xb[(size_t)ic * NPIX + yy * 64 + xx];
                float h, l;
                tf32split(v, h, l);
                Bh[kk * BST + nn] = h;
                Bl[kk * BST + nn] = l;
            }
        }
        __syncthreads();

        if (!CONV && k0 + 32 < K) {
#pragma unroll
            for (int t = 0; t < NF; t++) {
                int i = tid + t * 256;
                int kk = i / (NF * 8), nq = i % (NF * 8);
                pb[t] = *(const float4*)&Xb[(size_t)(k0 + 32 + kk) * NPIX + nbase + nq * 4];
            }
        }

#pragma unroll
        for (int ks = 0; ks < 4; ks++) {
            const int kb = ks * 8 + (lane & 3);
            uint32_t bh[NF][2], bl[NF][2];
#pragma unroll
            for (int nf = 0; nf < NF; nf++) {
                int col = wn * (NF * 8) + nf * 8 + (lane >> 2);
                bh[nf][0] = __float_as_uint(Bh[kb * BST + col]);
                bh[nf][1] = __float_as_uint(Bh[(kb + 4) * BST + col]);
                bl[nf][0] = __float_as_uint(Bl[kb * BST + col]);
                bl[nf][1] = __float_as_uint(Bl[(kb + 4) * BST + col]);
            }
#pragma unroll
            for (int mf = 0; mf < 2; mf++) {
                uint32_t ah[4], al[4];
                ldsm4(ah, aAh[mf] + ks * 32);
                ldsm4(al, aAl[mf] + ks * 32);
#pragma unroll
                for (int nf = 0; nf < NF; nf++) {
                    mma8(acc[mf][nf], ah, bh[nf]);
                    mma8(acc[mf][nf], ah, bl[nf]);
                    mma8(acc[mf][nf], al, bh[nf]);
                }
            }
        }
        __syncthreads();
    }

    // ---- epilogue ----
#pragma unroll
    for (int mf = 0; mf < 2; mf++) {
        int o0 = obase + wm * 32 + mf * 16 + (lane >> 2);
        int o1 = o0 + 8;
        float bi0 = bias ? bias[o0] : 0.f;
        float bi1 = bias ? bias[o1] : 0.f;
        size_t r0 = ((size_t)b * O + o0) * NPIX;
        size_t r1 = ((size_t)b * O + o1) * NPIX;
#pragma unroll
        for (int nf = 0; nf < NF; nf++) {
            int n = nbase + wn * (NF * 8) + nf * 8 + 2 * (lane & 3);
            float v00 = acc[mf][nf][0] + bi0, v01 = acc[mf][nf][1] + bi0;
            float v10 = acc[mf][nf][2] + bi1, v11 = acc[mf][nf][3] + bi1;
            if (ACT == 1) {
                v00 = v00 > 0.f ? v00 : 0.2f * v00; v01 = v01 > 0.f ? v01 : 0.2f * v01;
                v10 = v10 > 0.f ? v10 : 0.2f * v10; v11 = v11 > 0.f ? v11 : 0.2f * v11;
            }
            if (ACT == 2) { v00 = elup1(v00); v01 = elup1(v01); v10 = elup1(v10); v11 = elup1(v11); }
            if (mul) {
                v00 *= mul[r0 + n]; v01 *= mul[r0 + n + 1];
                v10 *= mul[r1 + n]; v11 *= mul[r1 + n + 1];
            }
            *(float2*)&Y[r0 + n] = make_float2(v00, v01);
            *(float2*)&Y[r1 + n] = make_float2(v10, v11);
        }
    }
}

template<int ACT, bool CONV, int NF>
__global__ __launch_bounds__(256, 2) void gemm_tc(
    const float* __restrict__ Ahi, const float* __restrict__ Alo,
    const float* __restrict__ X,
    const float* __restrict__ bias, const float* __restrict__ mul,
    float* __restrict__ Y, int O, int K)
{
    gemm_core<ACT, CONV, NF>(Ahi, Alo, X, bias, mul, Y, O, K, blockIdx.y);
}

// fused q + kv GEMM: y 0-3 -> q (elup1, bias), y 4-11 -> kv
__global__ __launch_bounds__(256, 2) void gemm_qkv_k(
    const float* __restrict__ x, const float* __restrict__ bq,
    float* __restrict__ qout, float* __restrict__ kvout)
{
    if (blockIdx.y < 4)
        gemm_core<2, false, 4>(g_Whi + OFF_Q, g_Wlo + OFF_Q, x, bq, nullptr, qout, 256, 256, blockIdx.y);
    else
        gemm_core<0, false, 4>(g_Whi + OFF_A1, g_Wlo + OFF_A1, x, nullptr, nullptr, kvout, 512, 256, blockIdx.y - 4);
}

// ---------------- depthwise 3x3 SAME ----------------
__global__ __launch_bounds__(256) void dwconv_k(const float* __restrict__ W)
{
    __shared__ float sp[66][68];
    int c = blockIdx.x & 511, b = blockIdx.x >> 9;
    const float* Xc = g_kv + ((size_t)(b * 512 + c)) * NPIX;
    float* Oc = g_kvdw + ((size_t)(b * 512 + c)) * NPIX;

    for (int i = threadIdx.x; i < 66 * 66; i += 256) {
        int r = i / 66, col = i - r * 66;
        int y = r - 1, x = col - 1;
        sp[r][col] = (y >= 0 && y < 64 && x >= 0 && x < 64) ? Xc[y * 64 + x] : 0.f;
    }
    float w[9];
#pragma unroll
    for (int j = 0; j < 9; j++) w[j] = W[c * 9 + j];
    __syncthreads();

    bool isk = (c < 256);
    for (int i = threadIdx.x; i < 4096; i += 256) {
        int y = i >> 6, x = i & 63;
        float acc = 0.f;
#pragma unroll
        for (int dy = 0; dy < 3; dy++)
#pragma unroll
            for (int dx = 0; dx < 3; dx++)
                acc += w[dy * 3 + dx] * sp[y + dy][x + dx];
        Oc[i] = isk ? elup1(acc) : acc;
    }
}

// ---------------- attention phase 1 (TENSOR CORE): S_c = k^T v, ksum_c -------------
#define P1_SMEM_FLOATS (4 * 64 * 68 + 256)
__global__ __launch_bounds__(256, 2) void attn_chunk_sums_tc()
{
    extern __shared__ __align__(16) float sm[];
    float* Ah = sm;                 // [d][n] stride 68
    float* Al = Ah + 64 * 68;
    float* Bh = Al + 64 * 68;       // [n][e] stride 68
    float* Bl = Bh + 64 * 68;
    float* sred = Bl + 64 * 68;     // 256

    const int tid = threadIdx.x;
    const int lane = tid & 31, warp = tid >> 5;
    const int wn = warp & 3, wm = warp >> 2;
    int ch = blockIdx.x, h = blockIdx.y, b = blockIdx.z;
    bool rev = (h >= 2);
    int base = ch * 64;
    int bh_idx = b * NHEAD + h;

    for (int i = tid; i < 4096; i += 256) {
        int d = i >> 6, nn = i & 63;
        int p = rev ? (NPIX - 1 - (base + nn)) : (base + nn);
        size_t off = ((size_t)b * 512 + h * 64 + d) * NPIX + p;
        float kvk = g_kvdw[off];
        float kvv = g_kvdw[off + (size_t)256 * NPIX];
        float hh, ll;
        tf32split(kvk, hh, ll);
        Ah[d * 68 + nn] = hh; Al[d * 68 + nn] = ll;
        tf32split(kvv, hh, ll);
        Bh[nn * 68 + d] = hh; Bl[nn * 68 + d] = ll;
    }
    __syncthreads();

    float acc[2][2][4];
#pragma unroll
    for (int i = 0; i < 2; i++)
#pragma unroll
        for (int j = 0; j < 2; j++)
#pragma unroll
            for (int r = 0; r < 4; r++) acc[i][j][r] = 0.f;

#pragma unroll
    for (int ks = 0; ks < 8; ks++) {
        const int kb = ks * 8 + (lane & 3);
        uint32_t bh2[2][2], bl2[2][2];
#pragma unroll
        for (int nf = 0; nf < 2; nf++) {
            int col = wn * 16 + nf * 8 + (lane >> 2);
            bh2[nf][0] = __float_as_uint(Bh[kb * 68 + col]);
            bh2[nf][1] = __float_as_uint(Bh[(kb + 4) * 68 + col]);
            bl2[nf][0] = __float_as_uint(Bl[kb * 68 + col]);
            bl2[nf][1] = __float_as_uint(Bl[(kb + 4) * 68 + col]);
        }
#pragma unroll
        for (int mf = 0; mf < 2; mf++) {
            int row = wm * 32 + mf * 16 + (lane >> 2);
            uint32_t ah[4], al[4];
            ah[0] = __float_as_uint(Ah[row * 68 + kb]);
            ah[1] = __float_as_uint(Ah[(row + 8) * 68 + kb]);
            ah[2] = __float_as_uint(Ah[row * 68 + kb + 4]);
            ah[3] = __float_as_uint(Ah[(row + 8) * 68 + kb + 4]);
            al[0] = __float_as_uint(Al[row * 68 + kb]);
            al[1] = __float_as_uint(Al[(row + 8) * 68 + kb]);
            al[2] = __float_as_uint(Al[row * 68 + kb + 4]);
            al[3] = __float_as_uint(Al[(row + 8) * 68 + kb + 4]);
#pragma unroll
            for (int nf = 0; nf < 2; nf++) {
                mma8(acc[mf][nf], ah, bh2[nf]);
                mma8(acc[mf][nf], ah, bl2[nf]);
                mma8(acc[mf][nf], al, bh2[nf]);
            }
        }
    }

    float* Sg = g_S + ((size_t)(bh_idx * NCHUNK + ch)) * 4096;
#pragma unroll
    for (int mf = 0; mf < 2; mf++) {
        int d0 = wm * 32 + mf * 16 + (lane >> 2);
        int d1 = d0 + 8;
#pragma unroll
        for (int nf = 0; nf < 2; nf++) {
            int e = wn * 16 + nf * 8 + 2 * (lane & 3);
            *(float2*)&Sg[d0 * 64 + e] = make_float2(acc[mf][nf][0], acc[mf][nf][1]);
            *(float2*)&Sg[d1 * 64 + e] = make_float2(acc[mf][nf][2], acc[mf][nf][3]);
        }
    }

    {
        int d = tid & 63, g = tid >> 6;
        float part = 0.f;
#pragma unroll
        for (int t = 0; t < 16; t++) {
            int nn = g * 16 + t;
            part += Ah[d * 68 + nn] + Al[d * 68 + nn];
        }
        sred[g * 64 + d] = part;
    }
    __syncthreads();
    if (tid < 64)
        g_ksum[(bh_idx * NCHUNK + ch) * 64 + tid] =
            sred[tid] + sred[64 + tid] + sred[128 + tid] + sred[192 + tid];
}

// ---------------- attention phase 2 ----------------
__global__ __launch_bounds__(256) void attn_prefix_k()
{
    int bh = blockIdx.y;
    int e = blockIdx.x * 256 + threadIdx.x;
    float* Sg = g_S + (size_t)bh * NCHUNK * 4096;
    float run = 0.f;
#pragma unroll 4
    for (int c = 0; c < NCHUNK; c++) {
        float v = Sg[(size_t)c * 4096 + e];
        Sg[(size_t)c * 4096 + e] = run;
        run += v;
    }
    if (blockIdx.x == 0 && threadIdx.x < 64) {
        int d = threadIdx.x;
        float r2 = 0.f;
        for (int c = 0; c < NCHUNK; c++) {
            float v = g_ksum[(bh * NCHUNK + c) * 64 + d];
            g_ksum[(bh * NCHUNK + c) * 64 + d] = r2;
            r2 += v;
        }
    }
}

// ---------------- attention phase 3 ----------------
#define P3_SMEM_FLOATS (4 * 64 * 68 + 64 + 64 + 256)
__global__ __launch_bounds__(256) void attn_out_k()
{
    extern __shared__ __align__(16) float sm[];
    float* sqT = sm;
    float* skv = sm + 4352;
    float* sAT = sm + 8704;
    float* sS  = sm + 13056;
    float* sks   = sm + 17408;
    float* srden = sm + 17472;
    float* sred  = sm + 17536;

    int tid = threadIdx.x;
    int ch = blockIdx.x, h = blockIdx.y, b = blockIdx.z;
    bool rev = (h >= 2);
    int base = ch * 64;
    int bh = b * NHEAD + h;

    for (int i = tid; i < 4096; i += 256) {
        int d = i >> 6, nn = i & 63;
        int p = rev ? (NPIX - 1 - (base + nn)) : (base + nn);
        sqT[d * 68 + nn] = g_q[((size_t)b * 256 + h * 64 + d) * NPIX + p];
        skv[d * 68 + nn] = g_kvdw[((size_t)b * 512 + h * 64 + d) * NPIX + p];
    }
    {
        const float* Sg = g_S + ((size_t)(bh * NCHUNK + ch)) * 4096;
        for (int i = tid; i < 4096; i += 256) sS[(i >> 6) * 68 + (i & 63)] = Sg[i];
    }
    if (tid < 64) sks[tid] = g_ksum[(bh * NCHUNK + ch) * 64 + tid];
    __syncthreads();

    {
        int n0 = (tid & 15) * 4, m0 = (tid >> 4) * 4;
        float a[4][4];
#pragma unroll
        for (int i = 0; i < 4; i++)
#pragma unroll
            for (int j = 0; j < 4; j++) a[i][j] = 0.f;
        for (int d = 0; d < 64; d++) {
            float4 q4 = *(const float4*)&sqT[d * 68 + n0];
            float4 k4 = *(const float4*)&skv[d * 68 + m0];
            float kv[4] = {k4.x, k4.y, k4.z, k4.w};
            float qv[4] = {q4.x, q4.y, q4.z, q4.w};
#pragma unroll
            for (int i = 0; i < 4; i++)
#pragma unroll
                for (int j = 0; j < 4; j++) a[i][j] += kv[i] * qv[j];
        }
        __syncthreads();
#pragma unroll
        for (int i = 0; i < 4; i++)
#pragma unroll
            for (int j = 0; j < 4; j++)
                sAT[(m0 + i) * 68 + (n0 + j)] = (m0 + i <= n0 + j) ? a[i][j] : 0.f;
    }
    for (int i = tid; i < 4096; i += 256) {
        int e = i >> 6, mm = i & 63;
        int p = rev ? (NPIX - 1 - (base + mm)) : (base + mm);
        skv[mm * 68 + e] = g_kvdw[((size_t)b * 512 + 256 + h * 64 + e) * NPIX + p];
    }
    __syncthreads();
    {
        int n = tid & 63, g = tid >> 6;
        float part = 0.f;
#pragma unroll
        for (int t = 0; t < 16; t++) {
            int m = g * 16 + t;
            part += sAT[m * 68 + n] + sqT[m * 68 + n] * sks[m];
        }
        sred[g * 64 + n] = part;
    }
    __syncthreads();

    int n0 = (tid & 15) * 4, e0 = (tid >> 4) * 4;
    float acc[4][4];
#pragma unroll
    for (int i = 0; i < 4; i++)
#pragma unroll
        for (int j = 0; j < 4; j++) acc[i][j] = 0.f;
    for (int m = 0; m < 64; m++) {
        float4 a4 = *(const float4*)&sAT[m * 68 + n0];
        float4 v4 = *(const float4*)&skv[m * 68 + e0];
        float vv[4] = {v4.x, v4.y, v4.z, v4.w};
        float av[4] = {a4.x, a4.y, a4.z, a4.w};
#pragma unroll
        for (int i = 0; i < 4; i++)
#pragma unroll
            for (int j = 0; j < 4; j++) acc[i][j] += vv[i] * av[j];
    }
    for (int d = 0; d < 64; d++) {
        float4 q4 = *(const float4*)&sqT[d * 68 + n0];
        float4 s4 = *(const float4*)&sS[d * 68 + e0];
        float sv4[4] = {s4.x, s4.y, s4.z, s4.w};
        float qv[4] = {q4.x, q4.y, q4.z, q4.w};
#pragma unroll
        for (int i = 0; i < 4; i++)
#pragma unroll
            for (int j = 0; j < 4; j++) acc[i][j] += sv4[i] * qv[j];
    }
    __syncthreads();
#pragma unroll
    for (int i = 0; i < 4; i++)
#pragma unroll
        for (int j = 0; j < 4; j++) sAT[(e0 + i) * 68 + (n0 + j)] = acc[i][j];
    if (tid < 64)
        srden[tid] = 1.f / (1e-6f + sred[tid] + sred[64 + tid] + sred[128 + tid] + sred[192 + tid]);
    __syncthreads();

    for (int i = tid; i < 4096; i += 256) {
        int e = i >> 6, nn = i & 63;
        int p = rev ? (NPIX - 1 - (base + nn)) : (base + nn);
        g_attn[((size_t)b * 256 + h * 64 + e) * NPIX + p] = sAT[e * 68 + nn] * srden[nn];
    }
}

// ---------------- launch ----------------
#define SMEM_TC4 ((2 * 64 * 36 + 2 * 32 * 132) * 4)

extern "C" void kernel_launch(void* const* d_in, const int* in_sizes, int n_in,
                              void* d_out, int out_size)
{
    (void)in_sizes; (void)n_in; (void)out_size;
    const float* x   = (const float*)d_in[0];
    const float* Wq  = (const float*)d_in[1];
    const float* bq  = (const float*)d_in[2];
    const float* Wa1 = (const float*)d_in[3];
    const float* Wdw = (const float*)d_in[4];
    const float* Wo  = (const float*)d_in[5];
    const float* bo  = (const float*)d_in[6];
    const float* Wg1 = (const float*)d_in[7];
    const float* bg1 = (const float*)d_in[8];
    const float* Wg2 = (const float*)d_in[9];
    const float* bg2 = (const float*)d_in[10];
    const float* Wg3 = (const float*)d_in[11];
    const float* bg3 = (const float*)d_in[12];
    float* out = (float*)d_out;

    float *qb, *kvb, *attnb, *g1b, *g2b, *gatedb, *whi, *wlo;
    cudaGetSymbolAddress((void**)&qb,    g_q);
    cudaGetSymbolAddress((void**)&kvb,   g_kv);
    cudaGetSymbolAddress((void**)&attnb, g_attn);
    cudaGetSymbolAddress((void**)&g1b,   g_g1);
    cudaGetSymbolAddress((void**)&g2b,   g_g2);
    cudaGetSymbolAddress((void**)&gatedb,g_gated);
    cudaGetSymbolAddress((void**)&whi,   g_Whi);
    cudaGetSymbolAddress((void**)&wlo,   g_Wlo);

    cudaFuncSetAttribute(gemm_qkv_k, cudaFuncAttributeMaxDynamicSharedMemorySize, SMEM_TC4);
    cudaFuncSetAttribute(gemm_tc<0, false, 4>, cudaFuncAttributeMaxDynamicSharedMemorySize, SMEM_TC4);
    cudaFuncSetAttribute(gemm_tc<1, false, 4>, cudaFuncAttributeMaxDynamicSharedMemorySize, SMEM_TC4);
    cudaFuncSetAttribute(gemm_tc<1, true,  4>, cudaFuncAttributeMaxDynamicSharedMemorySize, SMEM_TC4);
    cudaFuncSetAttribute(attn_chunk_sums_tc, cudaFuncAttributeMaxDynamicSharedMemorySize, P1_SMEM_FLOATS * 4);
    cudaFuncSetAttribute(attn_out_k, cudaFuncAttributeMaxDynamicSharedMemorySize, P3_SMEM_FLOATS * 4);

    dim3 blk(256);
    cudaStream_t s0 = 0, s1 = g_si.s1;

    // weights split (both branches need it)
    prep_split_k<<<dim3(512, 6), blk, 0, s0>>>(Wq, Wa1, Wg1, Wg2, Wg3, Wo);
    cudaEventRecord(g_si.evFork, s0);

    // ---- side branch: gate conv chain ----
    cudaStreamWaitEvent(s1, g_si.evFork, 0);
    gemm_tc<1, false, 4><<<dim3(32, 1, 2), blk, SMEM_TC4, s1>>>(whi + OFF_G1, wlo + OFF_G1, x, bg1, nullptr, g1b, 64, 256);
    gemm_tc<1, true,  4><<<dim3(32, 1, 2), blk, SMEM_TC4, s1>>>(whi + OFF_G2, wlo + OFF_G2, g1b, bg2, nullptr, g2b, 64, 576);
    cudaEventRecord(g_si.evGate, s1);

    // ---- main branch: q/kv (fused) -> dwconv -> attention ----
    gemm_qkv_k<<<dim3(32, 12, 2), blk, SMEM_TC4, s0>>>(x, bq, qb, kvb);
    dwconv_k<<<BATCH * 512, blk, 0, s0>>>(Wdw);
    attn_chunk_sums_tc<<<dim3(NCHUNK, NHEAD, BATCH), blk, P1_SMEM_FLOATS * 4, s0>>>();
    attn_prefix_k<<<dim3(16, BATCH * NHEAD), blk, 0, s0>>>();
    attn_out_k<<<dim3(NCHUNK, NHEAD, BATCH), blk, P3_SMEM_FLOATS * 4, s0>>>();

    // ---- join: g3 needs both attn (s0) and g2 (s1) ----
    cudaStreamWaitEvent(s0, g_si.evGate, 0);
    gemm_tc<0, false, 4><<<dim3(32, 4, 2), blk, SMEM_TC4, s0>>>(whi + OFF_G3, wlo + OFF_G3, g2b, bg3, attnb, gatedb, 256, 64);
    gemm_tc<0, false, 4><<<dim3(32, 4, 2), blk, SMEM_TC4, s0>>>(whi + OFF_O, wlo + OFF_O, gatedb, bo, nullptr, out, 256, 256);
}